// round 14
// baseline (speedup 1.0000x reference)
#include <cuda_runtime.h>
#include <cuda_fp16.h>
#include <math.h>
#include <stdint.h>

#define BS   4096
#define LEN  32
#define DIM  768
#define HID  384
#define ROWS (BS * LEN)          // 131072
#define LN_EPS 1e-5f

// ---- mma tiling ----
#define BK 32
#define NCHUNK (DIM / BK)        // 24
#define NT1 (DIM / 128)          // 6
#define NT2 (HID / 128)          // 3
#define ASTRIDE 40               // fp16 elems per smem row (80B, 16B-divisible)
#define TILE_B (128 * ASTRIDE * 2)   // 10240 bytes per 128-row split tile
#define STAGE_B (4 * TILE_B)         // qa2 kernel stage (A_hi,A_lo,B_hi,B_lo)
#define SRED_OFF (2 * STAGE_B)       // 81920 (qa2 kernel, unused there)
#define SMEM_DYN (SRED_OFF + 2048)   // 83968  (qa2 kernel)

// ---- fused kernel (M=64 tile) smem layout ----
#define FTILE_A_B (64 * ASTRIDE * 2)             // 5120
#define FSTAGE_B  (2 * FTILE_A_B + 2 * TILE_B)   // 30720
#define FSRED_OFF (2 * FSTAGE_B)                 // 61440
#define FSAL_OFF  (FSRED_OFF + 3 * 256 * 4)      // 64512
#define FSMEM_DYN (FSAL_OFF + 2 * 64 * 4)        // 65024 (x2 CTAs = 130KB)

// stage-1 combined grid layout
#define TR_BLOCKS   (24 * 24 * 3)            // 1728 transpose tiles
#define QAP_BLOCKS  (BS / 8)                 // 512 qa LN-split blocks
#define UW_BLOCKS   (HID / 8)                // 48 u/w blocks
#define S1_BLOCKS   (TR_BLOCKS + QAP_BLOCKS + UW_BLOCKS)
// stage-2 combined grid layout
#define QA2_BLOCKS  ((BS / 128) * (DIM / 128))   // 192
#define PV_ROWS_PER_BLOCK 64
#define PV_BLOCKS   (ROWS / PV_ROWS_PER_BLOCK)   // 2048
#define S2_BLOCKS   (QA2_BLOCKS + PV_BLOCKS)

// ---------------- scratch (device globals; no runtime allocation) ----------
__device__ float g_qa2[BS * DIM];
__device__ float g_logits[ROWS];
__device__ float g_u[HID];
__device__ float g_w[HID];
// pre-split operands (hi at 0, lo at +count)
__device__ __align__(16) __half g_vs[2 * (size_t)ROWS * DIM];   // LN(v) split
__device__ __align__(16) __half g_qs[2 * (size_t)BS * DIM];     // LN(qa) split
__device__ __align__(16) __half g_y [2 * (size_t)ROWS * DIM];   // v2*g split
// transposed+split weights, [split][n][k]
__device__ __align__(16) __half g_vpW_s[2 * DIM * DIM];
__device__ __align__(16) __half g_qpW_s[2 * DIM * DIM];
__device__ __align__(16) __half g_grW1_s[2 * HID * DIM];

__device__ __forceinline__ float gelu_exact(float x) {
    return 0.5f * x * (1.0f + erff(x * 0.70710678118654752440f));
}
__device__ __forceinline__ void mma_f16(float* d, const uint32_t* a, const uint32_t* b) {
    asm volatile(
        "mma.sync.aligned.m16n8k16.row.col.f32.f16.f16.f32 "
        "{%0,%1,%2,%3}, {%4,%5,%6,%7}, {%8,%9}, {%0,%1,%2,%3};"
        : "+f"(d[0]), "+f"(d[1]), "+f"(d[2]), "+f"(d[3])
        : "r"(a[0]), "r"(a[1]), "r"(a[2]), "r"(a[3]), "r"(b[0]), "r"(b[1]));
}
__device__ __forceinline__ void ldsm_x4(uint32_t* r, uint32_t addr) {
    asm volatile("ldmatrix.sync.aligned.m8n8.x4.shared.b16 {%0,%1,%2,%3}, [%4];"
                 : "=r"(r[0]), "=r"(r[1]), "=r"(r[2]), "=r"(r[3]) : "r"(addr));
}
#define CP16(dst, src) \
    asm volatile("cp.async.ca.shared.global [%0], [%1], 16;" :: "r"(dst), "l"(src))
#define CP_COMMIT() asm volatile("cp.async.commit_group;")
#define CP_WAIT0()  asm volatile("cp.async.wait_group 0;")

// ---------------- device helper: LN fold + fp16 split of one row ------------
__device__ __forceinline__ void ln_split_row(const float* __restrict__ X,
                                             const float* __restrict__ lng,
                                             const float* __restrict__ lnb,
                                             __half* __restrict__ Sh,
                                             __half* __restrict__ Sl,
                                             int row, int lane) {
    const float* x = X + (size_t)row * DIM;
    float4 xv[6];
    float s = 0.f, ss = 0.f;
#pragma unroll
    for (int i = 0; i < 6; i++) {
        xv[i] = *(const float4*)(x + i * 128 + lane * 4);
        s += xv[i].x + xv[i].y + xv[i].z + xv[i].w;
        ss = fmaf(xv[i].x, xv[i].x, ss);
        ss = fmaf(xv[i].y, xv[i].y, ss);
        ss = fmaf(xv[i].z, xv[i].z, ss);
        ss = fmaf(xv[i].w, xv[i].w, ss);
    }
    for (int o = 16; o; o >>= 1) {
        s  += __shfl_xor_sync(0xffffffffu, s,  o);
        ss += __shfl_xor_sync(0xffffffffu, ss, o);
    }
    float m = s / DIM;
    float rstd = rsqrtf(fmaxf(ss / DIM - m * m, 0.f) + LN_EPS);
#pragma unroll
    for (int i = 0; i < 6; i++) {
        int k = i * 128 + lane * 4;
        float4 g4 = *(const float4*)(lng + k);
        float4 b4 = *(const float4*)(lnb + k);
        float x0 = fmaf(xv[i].x - m, rstd * g4.x, b4.x);
        float x1 = fmaf(xv[i].y - m, rstd * g4.y, b4.y);
        float x2 = fmaf(xv[i].z - m, rstd * g4.z, b4.z);
        float x3 = fmaf(xv[i].w - m, rstd * g4.w, b4.w);
        __half2 h01 = __floats2half2_rn(x0, x1);
        __half2 h23 = __floats2half2_rn(x2, x3);
        float r0 = x0 - __low2float(h01), r1 = x1 - __high2float(h01);
        float r2 = x2 - __low2float(h23), r3 = x3 - __high2float(h23);
        __half2 l01 = __floats2half2_rn(r0, r1);
        __half2 l23 = __floats2half2_rn(r2, r3);
        size_t off = (size_t)row * DIM + k;
        *(uint2*)(Sh + off) = make_uint2(*(uint32_t*)&h01, *(uint32_t*)&h23);
        *(uint2*)(Sl + off) = make_uint2(*(uint32_t*)&l01, *(uint32_t*)&l23);
    }
}

// ---------------- stage 1: transposes + LN-split(qa) + u/w ------------------
__global__ void prep_stage1(const float* __restrict__ vpW,
                            const float* __restrict__ qpW,
                            const float* __restrict__ W1,
                            __half* __restrict__ vout,
                            __half* __restrict__ qout,
                            __half* __restrict__ w1out,
                            const float* __restrict__ qa,
                            const float* __restrict__ qp_g,
                            const float* __restrict__ qp_b,
                            __half* __restrict__ qsh, __half* __restrict__ qsl,
                            const float* __restrict__ gr_g,
                            const float* __restrict__ gr_b,
                            const float* __restrict__ gr_b1,
                            float* __restrict__ u, float* __restrict__ w) {
    int b = blockIdx.x;
    int tid = threadIdx.x;
    if (b < TR_BLOCKS) {
        int z = b / 576, rem = b % 576;
        const float* W; __half* Ws; int N;
        if (z == 0)      { W = vpW; Ws = vout;  N = DIM; }
        else if (z == 1) { W = qpW; Ws = qout;  N = DIM; }
        else             { W = W1;  Ws = w1out; N = HID; }
        int n0 = (rem % 24) * 32, k0 = (rem / 24) * 32;
        if (n0 >= N) return;
        __shared__ float t[32][33];
        int tx = tid & 31, ty = tid >> 5;   // 32 x 8
#pragma unroll
        for (int i = 0; i < 4; i++)
            t[ty + i * 8][tx] = W[(size_t)(k0 + ty + i * 8) * N + n0 + tx];
        __syncthreads();
        size_t ss = (size_t)N * DIM;
#pragma unroll
        for (int i = 0; i < 4; i++) {
            int n = n0 + ty + i * 8;
            float x = t[tx][ty + i * 8];
            __half hb = __float2half_rn(x);
            float r = x - __half2float(hb);
            __half lb = __float2half_rn(r);
            size_t o = (size_t)n * DIM + k0 + tx;
            Ws[o] = hb; Ws[ss + o] = lb;
        }
    } else if (b < TR_BLOCKS + QAP_BLOCKS) {
        int row = (b - TR_BLOCKS) * 8 + (tid >> 5);
        ln_split_row(qa, qp_g, qp_b, qsh, qsl, row, tid & 31);
    } else {
        int n = (b - TR_BLOCKS - QAP_BLOCKS) * 8 + (tid >> 5);
        if (n >= HID) return;
        int lane = tid & 31;
        float su = 0.f, sw = 0.f;
        for (int k = lane; k < DIM; k += 32) {
            float wv = W1[(size_t)k * HID + n];
            su = fmaf(gr_g[k], wv, su);
            sw = fmaf(gr_b[k], wv, sw);
        }
        for (int o = 16; o; o >>= 1) {
            su += __shfl_xor_sync(0xffffffffu, su, o);
            sw += __shfl_xor_sync(0xffffffffu, sw, o);
        }
        if (lane == 0) { u[n] = su; w[n] = sw + gr_b1[n]; }
    }
}

// ---------------- stage 2: qa2 GEMM tiles + LN-split(v), co-scheduled -------
__global__ __launch_bounds__(256, 2)
void stage2_kernel(const __half* __restrict__ Ah, const __half* __restrict__ Al,
                   const __half* __restrict__ Bh, const __half* __restrict__ Bl,
                   const float* __restrict__ bias,
                   float* __restrict__ C,
                   const float* __restrict__ v,
                   const float* __restrict__ vp_g,
                   const float* __restrict__ vp_b,
                   __half* __restrict__ vsh, __half* __restrict__ vsl) {
    extern __shared__ char smem[];
    int tid = threadIdx.x;

    if (blockIdx.x >= QA2_BLOCKS) {
        int row0 = (blockIdx.x - QA2_BLOCKS) * PV_ROWS_PER_BLOCK + (tid >> 5) * 8;
        int lane = tid & 31;
#pragma unroll
        for (int i = 0; i < 8; i++)
            ln_split_row(v, vp_g, vp_b, vsh, vsl, row0 + i, lane);
        return;
    }

    int wid = tid >> 5, lane = tid & 31;
    int warp_m = wid >> 2, warp_n = wid & 3;
    int g = lane >> 2, tig = lane & 3;
    int bm = (blockIdx.x % (BS / 128)) * 128;
    int bn = (blockIdx.x / (BS / 128)) * 128;

    uint32_t sbase = (uint32_t)__cvta_generic_to_shared(smem);
    int lrow = lane & 15;
    int lhk  = ((lane >> 4) & 1) * 8;
    uint32_t a_lane_off = (uint32_t)(((warp_m * 64 + lrow) * ASTRIDE + lhk) * 2);
    int bn_off = (lane & 7) + ((lane >> 4) & 1) * 8;
    int bk_off = ((lane >> 3) & 1) * 8;
    uint32_t b_lane_off = (uint32_t)(((warp_n * 32 + bn_off) * ASTRIDE + bk_off) * 2);

    int arow = tid >> 1, ahalf = tid & 1;
    uint32_t stg_lane = (uint32_t)((arow * ASTRIDE + ahalf * 16) * 2);
    size_t a_src_off = (size_t)(bm + arow) * DIM + ahalf * 16;
    size_t b_src_off = (size_t)(bn + arow) * DIM + ahalf * 16;

    float acc[4][4][4];
#pragma unroll
    for (int i = 0; i < 4; i++)
#pragma unroll
        for (int j = 0; j < 4; j++)
#pragma unroll
            for (int r = 0; r < 4; r++) acc[i][j][r] = 0.f;

    auto issue = [&](int cc) {
        int k0 = cc * BK;
        uint32_t dst = sbase + (uint32_t)(cc & 1) * STAGE_B + stg_lane;
        const __half* sh = Ah + a_src_off + k0;
        const __half* sl = Al + a_src_off + k0;
        CP16(dst, sh); CP16(dst + 16, sh + 8);
        CP16(dst + TILE_B, sl); CP16(dst + TILE_B + 16, sl + 8);
        const __half* th = Bh + b_src_off + k0;
        const __half* tl = Bl + b_src_off + k0;
        uint32_t dstb = dst + 2 * TILE_B;
        CP16(dstb, th); CP16(dstb + 16, th + 8);
        CP16(dstb + TILE_B, tl); CP16(dstb + TILE_B + 16, tl + 8);
        CP_COMMIT();
    };
    auto compute = [&](int st) {
        uint32_t base = sbase + (uint32_t)st * STAGE_B;
#pragma unroll
        for (int ks = 0; ks < 2; ks++) {
            uint32_t koff = (uint32_t)(ks * 16 * 2);
            uint32_t bfr[2][4][2];
#pragma unroll
            for (int sb = 0; sb < 2; sb++) {
                uint32_t bb = base + (2 + sb) * TILE_B + b_lane_off + koff;
#pragma unroll
                for (int p = 0; p < 2; p++) {
                    uint32_t r[4];
                    ldsm_x4(r, bb + (uint32_t)(p * 16 * ASTRIDE * 2));
                    bfr[sb][2 * p][0] = r[0]; bfr[sb][2 * p][1] = r[1];
                    bfr[sb][2 * p + 1][0] = r[2]; bfr[sb][2 * p + 1][1] = r[3];
                }
            }
            uint32_t afr[2][4][4];
#pragma unroll
            for (int sa = 0; sa < 2; sa++) {
                uint32_t ab = base + sa * TILE_B + a_lane_off + koff;
#pragma unroll
                for (int mt = 0; mt < 4; mt++)
                    ldsm_x4(afr[sa][mt], ab + (uint32_t)(mt * 16 * ASTRIDE * 2));
            }
#pragma unroll
            for (int mt = 0; mt < 4; mt++)
#pragma unroll
                for (int nt2 = 0; nt2 < 4; nt2++)
                    mma_f16(acc[mt][nt2], afr[0][mt], bfr[0][nt2]);
#pragma unroll
            for (int mt = 0; mt < 4; mt++)
#pragma unroll
                for (int nt2 = 0; nt2 < 4; nt2++)
                    mma_f16(acc[mt][nt2], afr[0][mt], bfr[1][nt2]);
#pragma unroll
            for (int mt = 0; mt < 4; mt++)
#pragma unroll
                for (int nt2 = 0; nt2 < 4; nt2++)
                    mma_f16(acc[mt][nt2], afr[1][mt], bfr[0][nt2]);
        }
    };

    issue(0);
    CP_WAIT0();
    __syncthreads();

    for (int cc = 0; cc < NCHUNK; cc++) {
        bool more = (cc + 1 < NCHUNK);
        if (more) issue(cc + 1);
        compute(cc & 1);
        if (more) { CP_WAIT0(); __syncthreads(); }
    }

#pragma unroll
    for (int mt = 0; mt < 4; mt++) {
#pragma unroll
        for (int nt2 = 0; nt2 < 4; nt2++) {
            int row = bm + warp_m * 64 + mt * 16 + g;
            int col = bn + warp_n * 32 + nt2 * 8 + tig * 2;
            float2 v0, v1;
            v0.x = gelu_exact(acc[mt][nt2][0] + bias[col]);
            v0.y = gelu_exact(acc[mt][nt2][1] + bias[col + 1]);
            v1.x = gelu_exact(acc[mt][nt2][2] + bias[col]);
            v1.y = gelu_exact(acc[mt][nt2][3] + bias[col + 1]);
            *(float2*)(C + (size_t)row * DIM + col) = v0;
            *(float2*)(C + (size_t)(row + 8) * DIM + col) = v1;
        }
    }
}

// ---------------- fused GEMM1+GEMM3 (M=64 tile, 2048 CTAs) ------------------
__global__ __launch_bounds__(256, 2)
void fused_gemm_kernel(const __half* __restrict__ Ah, const __half* __restrict__ Al,
                       const __half* __restrict__ Bh, const __half* __restrict__ Bl,
                       const __half* __restrict__ W1h, const __half* __restrict__ W1l,
                       const float* __restrict__ bias,
                       const float* __restrict__ gcol,
                       const float* __restrict__ qa2gate,
                       __half* __restrict__ Yh, __half* __restrict__ Yl,
                       const float* __restrict__ u, const float* __restrict__ wvec,
                       const float* __restrict__ w2, const float* __restrict__ b2,
                       float* __restrict__ logits) {
    extern __shared__ char smem[];
    const unsigned full = 0xffffffffu;
    int tid = threadIdx.x;
    int wid = tid >> 5, lane = tid & 31;
    int warp_m = wid >> 2, warp_n = wid & 3;   // 2 x 4; warp_m covers 32 rows
    int g = lane >> 2, tig = lane & 3;
    int bm = blockIdx.x * 64;

    uint32_t sbase = (uint32_t)__cvta_generic_to_shared(smem);
    int lrow = lane & 15;
    int lhk  = ((lane >> 4) & 1) * 8;
    uint32_t a_lane_off = (uint32_t)(((warp_m * 32 + lrow) * ASTRIDE + lhk) * 2);
    int bn_off = (lane & 7) + ((lane >> 4) & 1) * 8;
    int bk_off = ((lane >> 3) & 1) * 8;
    uint32_t b_lane_off = (uint32_t)(((warp_n * 32 + bn_off) * ASTRIDE + bk_off) * 2);

    // staging: A 64 rows, 4 threads/row x 8 halves; B 128 rows, 2 threads/row
    int arow4 = tid >> 2, aq = tid & 3;
    uint32_t stg_a = (uint32_t)((arow4 * ASTRIDE + aq * 8) * 2);
    size_t a_src4 = (size_t)(bm + arow4) * DIM + aq * 8;
    int brow = tid >> 1, bhalf = tid & 1;
    uint32_t stg_b = (uint32_t)((brow * ASTRIDE + bhalf * 16) * 2);

    float acc[2][4][4];
#pragma unroll
    for (int i = 0; i < 2; i++)
#pragma unroll
        for (int j = 0; j < 4; j++)
#pragma unroll
            for (int r = 0; r < 4; r++) acc[i][j][r] = 0.f;

    float rs[2][2], rss[2][2], rdt[2][2];
#pragma unroll
    for (int i = 0; i < 2; i++) {
        rs[i][0] = rs[i][1] = 0.f;
        rss[i][0] = rss[i][1] = 0.f;
        rdt[i][0] = rdt[i][1] = 0.f;
    }

    auto cp_a = [&](const __half* Ph, const __half* Pl, int k0, int st) {
        uint32_t dst = sbase + (uint32_t)st * FSTAGE_B + stg_a;
        CP16(dst, Ph + a_src4 + k0);
        CP16(dst + FTILE_A_B, Pl + a_src4 + k0);
    };
    auto cp_b = [&](const __half* Ph, const __half* Pl, size_t off, int st) {
        uint32_t dst = sbase + (uint32_t)st * FSTAGE_B + 2 * FTILE_A_B + stg_b;
        CP16(dst, Ph + off); CP16(dst + 16, Ph + off + 8);
        CP16(dst + TILE_B, Pl + off); CP16(dst + TILE_B + 16, Pl + off + 8);
    };
    auto compute = [&](int st) {
        uint32_t base = sbase + (uint32_t)st * FSTAGE_B;
#pragma unroll
        for (int ks = 0; ks < 2; ks++) {
            uint32_t koff = (uint32_t)(ks * 16 * 2);
            uint32_t bfr[2][4][2];
#pragma unroll
            for (int sb = 0; sb < 2; sb++) {
                uint32_t bb = base + 2 * FTILE_A_B + sb * TILE_B + b_lane_off + koff;
#pragma unroll
                for (int p = 0; p < 2; p++) {
                    uint32_t r[4];
                    ldsm_x4(r, bb + (uint32_t)(p * 16 * ASTRIDE * 2));
                    bfr[sb][2 * p][0] = r[0]; bfr[sb][2 * p][1] = r[1];
                    bfr[sb][2 * p + 1][0] = r[2]; bfr[sb][2 * p + 1][1] = r[3];
                }
            }
            uint32_t afr[2][2][4];
#pragma unroll
            for (int sa = 0; sa < 2; sa++) {
                uint32_t ab = base + sa * FTILE_A_B + a_lane_off + koff;
#pragma unroll
                for (int mt = 0; mt < 2; mt++)
                    ldsm_x4(afr[sa][mt], ab + (uint32_t)(mt * 16 * ASTRIDE * 2));
            }
#pragma unroll
            for (int mt = 0; mt < 2; mt++)
#pragma unroll
                for (int nt2 = 0; nt2 < 4; nt2++)
                    mma_f16(acc[mt][nt2], afr[0][mt], bfr[0][nt2]);
#pragma unroll
            for (int mt = 0; mt < 2; mt++)
#pragma unroll
                for (int nt2 = 0; nt2 < 4; nt2++)
                    mma_f16(acc[mt][nt2], afr[0][mt], bfr[1][nt2]);
#pragma unroll
            for (int mt = 0; mt < 2; mt++)
#pragma unroll
                for (int nt2 = 0; nt2 < 4; nt2++)
                    mma_f16(acc[mt][nt2], afr[1][mt], bfr[0][nt2]);
        }
    };

    // ================== PHASE 1: v2 / y / gate stats ==================
    {
        const int NCH = NT1 * NCHUNK;
        auto issue = [&](int cc) {
            int k0 = (cc % NCHUNK) * BK;
            int nt = cc / NCHUNK;
            int st = cc & 1;
            cp_a(Ah, Al, k0, st);
            cp_b(Bh, Bl, (size_t)(nt * 128 + brow) * DIM + k0 + bhalf * 16, st);
            CP_COMMIT();
        };
        issue(0); CP_WAIT0(); __syncthreads();
        for (int cc = 0; cc < NCH; cc++) {
            bool more = (cc + 1 < NCH);
            if (more) issue(cc + 1);
            compute(cc & 1);
            if (((cc + 1) % NCHUNK) == 0) {
                int bn = (cc / NCHUNK) * 128;
#pragma unroll
                for (int mt = 0; mt < 2; mt++) {
#pragma unroll
                    for (int nt2 = 0; nt2 < 4; nt2++) {
                        int row = bm + warp_m * 32 + mt * 16 + g;
                        int col = bn + warp_n * 32 + nt2 * 8 + tig * 2;
                        float2 v0, v1;
                        v0.x = gelu_exact(acc[mt][nt2][0] + bias[col]);
                        v0.y = gelu_exact(acc[mt][nt2][1] + bias[col + 1]);
                        v1.x = gelu_exact(acc[mt][nt2][2] + bias[col]);
                        v1.y = gelu_exact(acc[mt][nt2][3] + bias[col + 1]);
                        float2 g2 = *(const float2*)(gcol + col);
                        float y00 = v0.x * g2.x, y01 = v0.y * g2.y;
                        float y10 = v1.x * g2.x, y11 = v1.y * g2.y;
                        __half2 h0 = __floats2half2_rn(y00, y01);
                        __half2 h1 = __floats2half2_rn(y10, y11);
                        __half2 l0 = __floats2half2_rn(y00 - __low2float(h0),
                                                       y01 - __high2float(h0));
                        __half2 l1 = __floats2half2_rn(y10 - __low2float(h1),
                                                       y11 - __high2float(h1));
                        size_t o0 = (size_t)row * DIM + col;
                        size_t o1 = (size_t)(row + 8) * DIM + col;
                        *(uint32_t*)(Yh + o0) = *(uint32_t*)&h0;
                        *(uint32_t*)(Yh + o1) = *(uint32_t*)&h1;
                        *(uint32_t*)(Yl + o0) = *(uint32_t*)&l0;
                        *(uint32_t*)(Yl + o1) = *(uint32_t*)&l1;
                        int b0 = row >> 5;
                        float2 q = *(const float2*)(qa2gate + (size_t)b0 * DIM + col);
                        rs[mt][0]  += v0.x + v0.y;
                        rss[mt][0] += v0.x * v0.x + v0.y * v0.y;
                        rdt[mt][0] += v0.x * q.x + v0.y * q.y;
                        rs[mt][1]  += v1.x + v1.y;
                        rss[mt][1] += v1.x * v1.x + v1.y * v1.y;
                        rdt[mt][1] += v1.x * q.x + v1.y * q.y;
                        acc[mt][nt2][0] = 0.f; acc[mt][nt2][1] = 0.f;
                        acc[mt][nt2][2] = 0.f; acc[mt][nt2][3] = 0.f;
                    }
                }
            }
            if (more) { CP_WAIT0(); __syncthreads(); }
        }
    }

    // ---- gate/LN-fold stats -> smem alpha/m2 (64 rows) ----
    float* sal = (float*)(smem + FSAL_OFF);
    float* sm2 = sal + 64;
    {
#pragma unroll
        for (int off = 1; off <= 2; off <<= 1) {
#pragma unroll
            for (int mt = 0; mt < 2; mt++) {
#pragma unroll
                for (int h = 0; h < 2; h++) {
                    rs[mt][h]  += __shfl_xor_sync(full, rs[mt][h],  off);
                    rss[mt][h] += __shfl_xor_sync(full, rss[mt][h], off);
                    rdt[mt][h] += __shfl_xor_sync(full, rdt[mt][h], off);
                }
            }
        }
        float* sred = (float*)(smem + FSRED_OFF);
        __syncthreads();   // also orders phase-1 Y stores before phase-2 reads
        if (tig == 0) {
#pragma unroll
            for (int mt = 0; mt < 2; mt++) {
#pragma unroll
                for (int h = 0; h < 2; h++) {
                    int r = warp_m * 32 + mt * 16 + g + h * 8;
                    sred[0 * 256 + warp_n * 64 + r] = rs[mt][h];
                    sred[1 * 256 + warp_n * 64 + r] = rss[mt][h];
                    sred[2 * 256 + warp_n * 64 + r] = rdt[mt][h];
                }
            }
        }
        __syncthreads();
        if (tid < 64) {
            float s = 0.f, ss2 = 0.f, dt = 0.f;
#pragma unroll
            for (int w = 0; w < 4; w++) {
                s   += sred[0 * 256 + w * 64 + tid];
                ss2 += sred[1 * 256 + w * 64 + tid];
                dt  += sred[2 * 256 + w * 64 + tid];
            }
            float m = s / DIM;
            float var = fmaxf(ss2 / DIM - m * m, 0.f);
            float gate = tanhf(dt);
            sm2[tid] = m;
            sal[tid] = gate * rsqrtf(gate * gate * var + LN_EPS);
        }
        __syncthreads();
    }

    // per-row constants for phase 2
    float alp[2][2], mm[2][2];
#pragma unroll
    for (int mt = 0; mt < 2; mt++) {
        int r0 = warp_m * 32 + mt * 16 + g;
        alp[mt][0] = sal[r0];     mm[mt][0] = sm2[r0];
        alp[mt][1] = sal[r0 + 8]; mm[mt][1] = sm2[r0 + 8];
    }

    // ================== PHASE 2: logits ==================
    float dotacc = 0.f;
    {
        const int NCH = NT2 * NCHUNK;
        auto issue = [&](int cc) {
            int k0 = (cc % NCHUNK) * BK;
            int nt = cc / NCHUNK;
            int st = cc & 1;
            cp_a(Yh, Yl, k0, st);
            cp_b(W1h, W1l, (size_t)(nt * 128 + brow) * DIM + k0 + bhalf * 16, st);
            CP_COMMIT();
        };
        issue(0); CP_WAIT0(); __syncthreads();
        for (int cc = 0; cc < NCH; cc++) {
            bool more = (cc + 1 < NCH);
            if (more) issue(cc + 1);
            compute(cc & 1);
            if (((cc + 1) % NCHUNK) == 0) {
                int bn = (cc / NCHUNK) * 128;
                float part[2][2];
#pragma unroll
                for (int mt = 0; mt < 2; mt++) { part[mt][0] = 0.f; part[mt][1] = 0.f; }
#pragma unroll
                for (int mt = 0; mt < 2; mt++) {
#pragma unroll
                    for (int nt2 = 0; nt2 < 4; nt2++) {
                        int n0 = bn + warp_n * 32 + nt2 * 8 + tig * 2;
                        float u0 = u[n0], u1 = u[n0 + 1];
                        float wv0 = wvec[n0], wv1 = wvec[n0 + 1];
                        float w20 = w2[n0], w21 = w2[n0 + 1];
                        float h00 = alp[mt][0] * (acc[mt][nt2][0] - mm[mt][0] * u0) + wv0;
                        float h01 = alp[mt][0] * (acc[mt][nt2][1] - mm[mt][0] * u1) + wv1;
                        float h10 = alp[mt][1] * (acc[mt][nt2][2] - mm[mt][1] * u0) + wv0;
                        float h11 = alp[mt][1] * (acc[mt][nt2][3] - mm[mt][1] * u1) + wv1;
                        part[mt][0] += gelu_exact(h00) * w20 + gelu_exact(h01) * w21;
                        part[mt][1] += gelu_exact(h10) * w20 + gelu_exact(h11) * w21;
                        acc[mt][nt2][0] = 0.f; acc[mt][nt2][1] = 0.f;
                        acc[mt][nt2][2] = 0.f; acc[mt][nt2][3] = 0.f;
                    }
                }
#pragma unroll
                for (int off = 1; off <= 2; off <<= 1) {
#pragma unroll
                    for (int mt = 0; mt < 2; mt++) {
                        part[mt][0] += __shfl_xor_sync(full, part[mt][0], off);
                        part[mt][1] += __shfl_xor_sync(full, part[mt][1], off);
                    }
                }
                float* sr = (float*)(smem + FSRED_OFF);
                if (tig == 0) {
#pragma unroll
                    for (int mt = 0; mt < 2; mt++) {
                        int r = warp_m * 32 + mt * 16 + g;
                        sr[warp_n * 64 + r] = part[mt][0];
                        sr[warp_n * 64 + r + 8] = part[mt][1];
                    }
                }
                __syncthreads();
                if (tid < 64)
                    dotacc += ((sr[tid] + sr[64 + tid]) + (sr[128 + tid] + sr[192 + tid]));
                __syncthreads();
            }
            if (more) { CP_WAIT0(); __syncthreads(); }
        }
    }

    if (tid < 64)
        logits[bm + tid] = dotacc + b2[0];
}

// ---------------- finalize: shared gaussian kern, warp-parallel search ------
#define OFF_GS     0
#define OFF_MAXIDX (BS * LEN)
#define OFF_START  (BS * LEN + BS * 2)
#define OFF_END    (BS * LEN + BS * 3)
#define OFF_MASK   (BS * LEN + BS * 4)
#define OFF_ORIKEY (BS * LEN * 2 + BS * 4)

__global__ void finalize_kernel(const float* __restrict__ sigma_ptr,
                                float* __restrict__ out) {
    const unsigned full = 0xffffffffu;
    int tid = threadIdx.x;
    int warp = tid >> 5, lane = tid & 31;

    __shared__ double kraw[5];
    __shared__ double kern_s[5];
    if (tid < 5) {
        double sigma = (double)(*sigma_ptr);
        double x = (double)(tid - 2) / sigma;
        kraw[tid] = exp(-0.5 * x * x);
    }
    __syncthreads();
    if (tid < 5) {
        double ks = kraw[0] + kraw[1] + kraw[2] + kraw[3] + kraw[4];
        kern_s[tid] = kraw[tid] / ks;
    }
    __syncthreads();
    double kern[5];
#pragma unroll
    for (int j = 0; j < 5; j++) kern[j] = kern_s[j];

    int b = blockIdx.x * 8 + warp;
    float logit_f = g_logits[b * LEN + lane];
    double logit = (double)logit_f;

    double m = logit;
    for (int o = 16; o; o >>= 1) m = fmax(m, __shfl_xor_sync(full, m, o));
    double e = exp(logit - m);
    double s = e;
    for (int o = 16; o; o >>= 1) s += __shfl_xor_sync(full, s, o);
    double kp = e / s;

    double sm = 0.0;
#pragma unroll
    for (int j = 0; j < 5; j++) {
        int src = lane + j - 2;
        double v = __shfl_sync(full, kp, src & 31);
        if (src >= 0 && src < LEN) sm += kern[j] * v;
    }

    double mg = sm;
    for (int o = 16; o; o >>= 1) mg = fmax(mg, __shfl_xor_sync(full, mg, o));
    double eg = exp(sm - mg);
    double sg = eg;
    for (int o = 16; o; o >>= 1) sg += __shfl_xor_sync(full, sg, o);
    double gs = eg / sg;

    double bv = gs; int bi = lane;
    for (int o = 16; o; o >>= 1) {
        double ov = __shfl_xor_sync(full, bv, o);
        int    oi = __shfl_xor_sync(full, bi, o);
        if (ov > bv || (ov == bv && oi < bi)) { bv = ov; bi = oi; }
    }
    int amax = bi;

    double cs = gs;
#pragma unroll
    for (int off = 1; off < 32; off <<= 1) {
        double t = __shfl_up_sync(full, cs, off);
        if (lane >= off) cs += t;
    }

    double bestv = -INFINITY;
    int bestc = 1 << 20;
#pragma unroll
    for (int r = 0; r < 3; r++) {
        int c = lane + r * 32;
        int w, st;
        if (c < 32)      { w = 1; st = c; }
        else if (c < 62) { w = 3; st = c - 32; }
        else             { w = 5; st = c - 62; }
        bool valid = (c < 90);
        double hi = __shfl_sync(full, cs, (st + w - 1) & 31);
        double lo = __shfl_sync(full, cs, (st - 1) & 31);
        double sum = hi - ((st > 0) ? lo : 0.0);
        bool contains = (amax >= st) && (amax < st + w);
        double val = (valid && contains) ? sum : -INFINITY;
        if (val > bestv || (val == bestv && c < bestc)) { bestv = val; bestc = c; }
    }
    for (int off = 16; off; off >>= 1) {
        double ov = __shfl_xor_sync(full, bestv, off);
        int    oc = __shfl_xor_sync(full, bestc, off);
        if (ov > bestv || (ov == bestv && oc < bestc)) { bestv = ov; bestc = oc; }
    }
    int s0, e0;
    {
        int c = bestc, w, st;
        if (c < 32)      { w = 1; st = c; }
        else if (c < 62) { w = 3; st = c - 32; }
        else             { w = 5; st = c - 62; }
        s0 = st; e0 = st + w;
    }

    out[OFF_GS + b * LEN + lane] = (float)gs;
    if (lane == 0) {
        out[OFF_MAXIDX + b * 2 + 0] = (float)s0;
        out[OFF_MAXIDX + b * 2 + 1] = (float)e0;
        out[OFF_START + b] = (float)s0 / 31.0f;
        out[OFF_END + b]   = (float)e0 / 31.0f;
    }
    out[OFF_MASK + b * LEN + lane] = (lane >= s0 && lane <= e0) ? 1.f : 0.f;
    out[OFF_ORIKEY + b * LEN + lane] = logit_f;
}

// ---------------- launch ----------------------------------------------------
extern "C" void kernel_launch(void* const* d_in, const int* in_sizes, int n_in,
                              void* d_out, int out_size) {
    const float* v       = (const float*)d_in[0];
    const float* qa      = (const float*)d_in[1];
    const float* vp_g    = (const float*)d_in[2];
    const float* vp_b    = (const float*)d_in[3];
    const float* vp_W    = (const float*)d_in[4];
    const float* vp_bias = (const float*)d_in[5];
    const float* qp_g    = (const float*)d_in[6];
    const float* qp_b    = (const float*)d_in[7];
    const float* qp_W    = (const float*)d_in[8];
    const float* qp_bias = (const float*)d_in[9];
    const float* gr_g    = (const float*)d_in[10];
    const float* gr_b    = (const float*)d_in[11];
    const float* gr_W1   = (const float*)d_in[12];
    const float* gr_b1   = (const float*)d_in[13];
    const float* gr_W2   = (const float*)d_in[14];
    const float* gr_b2   = (const float*)d_in[15];
    const float* sigma   = (const float*)d_in[16];
    float* out = (float*)d_out;

    void *p_qa2, *p_lg, *p_u, *p_w;
    void *p_vs, *p_qs, *p_y, *p_vpw, *p_qpw, *p_w1;
    cudaGetSymbolAddress(&p_qa2, g_qa2);
    cudaGetSymbolAddress(&p_lg,  g_logits);
    cudaGetSymbolAddress(&p_u,   g_u);
    cudaGetSymbolAddress(&p_w,   g_w);
    cudaGetSymbolAddress(&p_vs,  g_vs);
    cudaGetSymbolAddress(&p_qs,  g_qs);
    cudaGetSymbolAddress(&p_y,   g_y);
    cudaGetSymbolAddress(&p_vpw, g_vpW_s);
    cudaGetSymbolAddress(&p_qpw, g_qpW_s);
    cudaGetSymbolAddress(&p_w1,  g_grW1_s);

    __half* vs  = (__half*)p_vs;
    __half* qs  = (__half*)p_qs;
    __half* yy  = (__half*)p_y;
    __half* vpw = (__half*)p_vpw;
    __half* qpw = (__half*)p_qpw;
    __half* w1s = (__half*)p_w1;
    const size_t VN = (size_t)ROWS * DIM;
    const size_t QN = (size_t)BS * DIM;

    cudaFuncSetAttribute((const void*)stage2_kernel,
                         cudaFuncAttributeMaxDynamicSharedMemorySize, SMEM_DYN);
    cudaFuncSetAttribute((const void*)fused_gemm_kernel,
                         cudaFuncAttributeMaxDynamicSharedMemorySize, FSMEM_DYN);

    // [1] transposes + LN-split(qa) + u/w (all independent, one launch)
    prep_stage1<<<S1_BLOCKS, 256>>>(
        vp_W, qp_W, gr_W1, vpw, qpw, w1s,
        qa, qp_g, qp_b, qs, qs + QN,
        gr_g, gr_b, gr_b1, (float*)p_u, (float*)p_w);

    // [2] qa2 GEMM tiles + LN-split(v) co-scheduled (tensor + memory overlap)
    stage2_kernel<<<S2_BLOCKS, 256, SMEM_DYN>>>(
        qs, qs + QN, qpw, qpw + (size_t)DIM * DIM, qp_bias, (float*)p_qa2,
        v, vp_g, vp_b, vs, vs + VN);

    // [3] fused GEMM1+GEMM3, M=64 tiles (2048 CTAs -> ~7 full waves)
    fused_gemm_kernel<<<ROWS / 64, 256, FSMEM_DYN>>>(
        vs, vs + VN, vpw, vpw + (size_t)DIM * DIM,
        w1s, w1s + (size_t)HID * DIM,
        vp_bias, gr_g, (const float*)p_qa2,
        yy, yy + VN,
        (const float*)p_u, (const float*)p_w,
        gr_W2, gr_b2, (float*)p_lg);

    // [4] finalize
    finalize_kernel<<<BS / 8, 256>>>(sigma, out);
}

// round 15
// speedup vs baseline: 1.0184x; 1.0184x over previous
#include <cuda_runtime.h>
#include <cuda_fp16.h>
#include <math.h>
#include <stdint.h>

#define BS   4096
#define LEN  32
#define DIM  768
#define HID  384
#define ROWS (BS * LEN)          // 131072
#define LN_EPS 1e-5f

// ---- mma tiling ----
#define BK 32
#define NCHUNK (DIM / BK)        // 24
#define NT1 (DIM / 128)          // 6
#define NT2 (HID / 128)          // 3
#define ASTRIDE 40               // fp16 elems per smem row (80B, 16B-divisible)
#define TILE_B (128 * ASTRIDE * 2)   // 10240 bytes per split tile
#define STAGE_B (4 * TILE_B)         // A_hi,A_lo,B_hi,B_lo = 40960
#define SRED_OFF (2 * STAGE_B)       // 81920
#define SAL_OFF  (SRED_OFF + 3 * 512 * 4)   // 88064
#define SMEM_DYN (SAL_OFF + 2 * 128 * 4)    // 89088  (x2 CTAs <= 228KB)

// stage-1 combined grid layout
#define TR_BLOCKS   (24 * 24 * 3)            // 1728 transpose tiles
#define QAP_BLOCKS  (BS / 8)                 // 512 qa LN-split blocks
#define UW_BLOCKS   (HID / 8)                // 48 u/w blocks
#define S1_BLOCKS   (TR_BLOCKS + QAP_BLOCKS + UW_BLOCKS)
// stage-2 combined grid layout
#define QA2_BLOCKS  ((BS / 128) * (DIM / 128))   // 192
#define PV_ROWS_PER_BLOCK 64
#define PV_BLOCKS   (ROWS / PV_ROWS_PER_BLOCK)   // 2048
#define S2_BLOCKS   (QA2_BLOCKS + PV_BLOCKS)

// ---------------- scratch (device globals; no runtime allocation) ----------
__device__ float g_qa2[BS * DIM];
__device__ float g_logits[ROWS];
__device__ float g_u[HID];
__device__ float g_w[HID];
// pre-split operands (hi at 0, lo at +count)
__device__ __align__(16) __half g_vs[2 * (size_t)ROWS * DIM];   // LN(v) split
__device__ __align__(16) __half g_qs[2 * (size_t)BS * DIM];     // LN(qa) split
__device__ __align__(16) __half g_y [2 * (size_t)ROWS * DIM];   // v2*g split
// transposed+split weights, [split][n][k]
__device__ __align__(16) __half g_vpW_s[2 * DIM * DIM];
__device__ __align__(16) __half g_qpW_s[2 * DIM * DIM];
__device__ __align__(16) __half g_grW1_s[2 * HID * DIM];

__device__ __forceinline__ float gelu_exact(float x) {
    return 0.5f * x * (1.0f + erff(x * 0.70710678118654752440f));
}
__device__ __forceinline__ void mma_f16(float* d, const uint32_t* a, const uint32_t* b) {
    asm volatile(
        "mma.sync.aligned.m16n8k16.row.col.f32.f16.f16.f32 "
        "{%0,%1,%2,%3}, {%4,%5,%6,%7}, {%8,%9}, {%0,%1,%2,%3};"
        : "+f"(d[0]), "+f"(d[1]), "+f"(d[2]), "+f"(d[3])
        : "r"(a[0]), "r"(a[1]), "r"(a[2]), "r"(a[3]), "r"(b[0]), "r"(b[1]));
}
__device__ __forceinline__ void ldsm_x4(uint32_t* r, uint32_t addr) {
    asm volatile("ldmatrix.sync.aligned.m8n8.x4.shared.b16 {%0,%1,%2,%3}, [%4];"
                 : "=r"(r[0]), "=r"(r[1]), "=r"(r[2]), "=r"(r[3]) : "r"(addr));
}
#define CP16(dst, src) \
    asm volatile("cp.async.ca.shared.global [%0], [%1], 16;" :: "r"(dst), "l"(src))
#define CP_COMMIT() asm volatile("cp.async.commit_group;")
#define CP_WAIT0()  asm volatile("cp.async.wait_group 0;")

// ---------------- device helper: LN fold + fp16 split of one row ------------
__device__ __forceinline__ void ln_split_row(const float* __restrict__ X,
                                             const float* __restrict__ lng,
                                             const float* __restrict__ lnb,
                                             __half* __restrict__ Sh,
                                             __half* __restrict__ Sl,
                                             int row, int lane) {
    const float* x = X + (size_t)row * DIM;
    float4 xv[6];
    float s = 0.f, ss = 0.f;
#pragma unroll
    for (int i = 0; i < 6; i++) {
        xv[i] = *(const float4*)(x + i * 128 + lane * 4);
        s += xv[i].x + xv[i].y + xv[i].z + xv[i].w;
        ss = fmaf(xv[i].x, xv[i].x, ss);
        ss = fmaf(xv[i].y, xv[i].y, ss);
        ss = fmaf(xv[i].z, xv[i].z, ss);
        ss = fmaf(xv[i].w, xv[i].w, ss);
    }
    for (int o = 16; o; o >>= 1) {
        s  += __shfl_xor_sync(0xffffffffu, s,  o);
        ss += __shfl_xor_sync(0xffffffffu, ss, o);
    }
    float m = s / DIM;
    float rstd = rsqrtf(fmaxf(ss / DIM - m * m, 0.f) + LN_EPS);
#pragma unroll
    for (int i = 0; i < 6; i++) {
        int k = i * 128 + lane * 4;
        float4 g4 = *(const float4*)(lng + k);
        float4 b4 = *(const float4*)(lnb + k);
        float x0 = fmaf(xv[i].x - m, rstd * g4.x, b4.x);
        float x1 = fmaf(xv[i].y - m, rstd * g4.y, b4.y);
        float x2 = fmaf(xv[i].z - m, rstd * g4.z, b4.z);
        float x3 = fmaf(xv[i].w - m, rstd * g4.w, b4.w);
        __half2 h01 = __floats2half2_rn(x0, x1);
        __half2 h23 = __floats2half2_rn(x2, x3);
        float r0 = x0 - __low2float(h01), r1 = x1 - __high2float(h01);
        float r2 = x2 - __low2float(h23), r3 = x3 - __high2float(h23);
        __half2 l01 = __floats2half2_rn(r0, r1);
        __half2 l23 = __floats2half2_rn(r2, r3);
        size_t off = (size_t)row * DIM + k;
        *(uint2*)(Sh + off) = make_uint2(*(uint32_t*)&h01, *(uint32_t*)&h23);
        *(uint2*)(Sl + off) = make_uint2(*(uint32_t*)&l01, *(uint32_t*)&l23);
    }
}

// ---------------- two rows concurrently (doubled MLP; per-row math identical)
__device__ __forceinline__ void ln_split_row2(const float* __restrict__ X,
                                              const float* __restrict__ lng,
                                              const float* __restrict__ lnb,
                                              __half* __restrict__ Sh,
                                              __half* __restrict__ Sl,
                                              int rowA, int rowB, int lane) {
    const float* xa = X + (size_t)rowA * DIM;
    const float* xb = X + (size_t)rowB * DIM;
    float4 va[6], vb[6];
#pragma unroll
    for (int i = 0; i < 6; i++) {
        va[i] = *(const float4*)(xa + i * 128 + lane * 4);
        vb[i] = *(const float4*)(xb + i * 128 + lane * 4);
    }
    float sa = 0.f, ssa = 0.f, sb = 0.f, ssb = 0.f;
#pragma unroll
    for (int i = 0; i < 6; i++) {
        sa += va[i].x + va[i].y + va[i].z + va[i].w;
        ssa = fmaf(va[i].x, va[i].x, ssa);
        ssa = fmaf(va[i].y, va[i].y, ssa);
        ssa = fmaf(va[i].z, va[i].z, ssa);
        ssa = fmaf(va[i].w, va[i].w, ssa);
        sb += vb[i].x + vb[i].y + vb[i].z + vb[i].w;
        ssb = fmaf(vb[i].x, vb[i].x, ssb);
        ssb = fmaf(vb[i].y, vb[i].y, ssb);
        ssb = fmaf(vb[i].z, vb[i].z, ssb);
        ssb = fmaf(vb[i].w, vb[i].w, ssb);
    }
    for (int o = 16; o; o >>= 1) {
        sa  += __shfl_xor_sync(0xffffffffu, sa,  o);
        ssa += __shfl_xor_sync(0xffffffffu, ssa, o);
        sb  += __shfl_xor_sync(0xffffffffu, sb,  o);
        ssb += __shfl_xor_sync(0xffffffffu, ssb, o);
    }
    float ma = sa / DIM;
    float ra = rsqrtf(fmaxf(ssa / DIM - ma * ma, 0.f) + LN_EPS);
    float mb = sb / DIM;
    float rb = rsqrtf(fmaxf(ssb / DIM - mb * mb, 0.f) + LN_EPS);
#pragma unroll
    for (int i = 0; i < 6; i++) {
        int k = i * 128 + lane * 4;
        float4 g4 = *(const float4*)(lng + k);
        float4 b4 = *(const float4*)(lnb + k);
        {
            float x0 = fmaf(va[i].x - ma, ra * g4.x, b4.x);
            float x1 = fmaf(va[i].y - ma, ra * g4.y, b4.y);
            float x2 = fmaf(va[i].z - ma, ra * g4.z, b4.z);
            float x3 = fmaf(va[i].w - ma, ra * g4.w, b4.w);
            __half2 h01 = __floats2half2_rn(x0, x1);
            __half2 h23 = __floats2half2_rn(x2, x3);
            float r0 = x0 - __low2float(h01), r1 = x1 - __high2float(h01);
            float r2 = x2 - __low2float(h23), r3 = x3 - __high2float(h23);
            __half2 l01 = __floats2half2_rn(r0, r1);
            __half2 l23 = __floats2half2_rn(r2, r3);
            size_t off = (size_t)rowA * DIM + k;
            *(uint2*)(Sh + off) = make_uint2(*(uint32_t*)&h01, *(uint32_t*)&h23);
            *(uint2*)(Sl + off) = make_uint2(*(uint32_t*)&l01, *(uint32_t*)&l23);
        }
        {
            float x0 = fmaf(vb[i].x - mb, rb * g4.x, b4.x);
            float x1 = fmaf(vb[i].y - mb, rb * g4.y, b4.y);
            float x2 = fmaf(vb[i].z - mb, rb * g4.z, b4.z);
            float x3 = fmaf(vb[i].w - mb, rb * g4.w, b4.w);
            __half2 h01 = __floats2half2_rn(x0, x1);
            __half2 h23 = __floats2half2_rn(x2, x3);
            float r0 = x0 - __low2float(h01), r1 = x1 - __high2float(h01);
            float r2 = x2 - __low2float(h23), r3 = x3 - __high2float(h23);
            __half2 l01 = __floats2half2_rn(r0, r1);
            __half2 l23 = __floats2half2_rn(r2, r3);
            size_t off = (size_t)rowB * DIM + k;
            *(uint2*)(Sh + off) = make_uint2(*(uint32_t*)&h01, *(uint32_t*)&h23);
            *(uint2*)(Sl + off) = make_uint2(*(uint32_t*)&l01, *(uint32_t*)&l23);
        }
    }
}

// ---------------- stage 1: transposes + LN-split(qa) + u/w ------------------
__global__ void prep_stage1(const float* __restrict__ vpW,
                            const float* __restrict__ qpW,
                            const float* __restrict__ W1,
                            __half* __restrict__ vout,
                            __half* __restrict__ qout,
                            __half* __restrict__ w1out,
                            const float* __restrict__ qa,
                            const float* __restrict__ qp_g,
                            const float* __restrict__ qp_b,
                            __half* __restrict__ qsh, __half* __restrict__ qsl,
                            const float* __restrict__ gr_g,
                            const float* __restrict__ gr_b,
                            const float* __restrict__ gr_b1,
                            float* __restrict__ u, float* __restrict__ w) {
    int b = blockIdx.x;
    int tid = threadIdx.x;
    if (b < TR_BLOCKS) {
        int z = b / 576, rem = b % 576;
        const float* W; __half* Ws; int N;
        if (z == 0)      { W = vpW; Ws = vout;  N = DIM; }
        else if (z == 1) { W = qpW; Ws = qout;  N = DIM; }
        else             { W = W1;  Ws = w1out; N = HID; }
        int n0 = (rem % 24) * 32, k0 = (rem / 24) * 32;
        if (n0 >= N) return;
        __shared__ float t[32][33];
        int tx = tid & 31, ty = tid >> 5;   // 32 x 8
#pragma unroll
        for (int i = 0; i < 4; i++)
            t[ty + i * 8][tx] = W[(size_t)(k0 + ty + i * 8) * N + n0 + tx];
        __syncthreads();
        size_t ss = (size_t)N * DIM;
#pragma unroll
        for (int i = 0; i < 4; i++) {
            int n = n0 + ty + i * 8;
            float x = t[tx][ty + i * 8];
            __half hb = __float2half_rn(x);
            float r = x - __half2float(hb);
            __half lb = __float2half_rn(r);
            size_t o = (size_t)n * DIM + k0 + tx;
            Ws[o] = hb; Ws[ss + o] = lb;
        }
    } else if (b < TR_BLOCKS + QAP_BLOCKS) {
        int row = (b - TR_BLOCKS) * 8 + (tid >> 5);
        ln_split_row(qa, qp_g, qp_b, qsh, qsl, row, tid & 31);
    } else {
        int n = (b - TR_BLOCKS - QAP_BLOCKS) * 8 + (tid >> 5);
        if (n >= HID) return;
        int lane = tid & 31;
        float su = 0.f, sw = 0.f;
        for (int k = lane; k < DIM; k += 32) {
            float wv = W1[(size_t)k * HID + n];
            su = fmaf(gr_g[k], wv, su);
            sw = fmaf(gr_b[k], wv, sw);
        }
        for (int o = 16; o; o >>= 1) {
            su += __shfl_xor_sync(0xffffffffu, su, o);
            sw += __shfl_xor_sync(0xffffffffu, sw, o);
        }
        if (lane == 0) { u[n] = su; w[n] = sw + gr_b1[n]; }
    }
}

// ---------------- stage 2: qa2 GEMM tiles + LN-split(v), co-scheduled -------
__global__ __launch_bounds__(256, 2)
void stage2_kernel(const __half* __restrict__ Ah, const __half* __restrict__ Al,
                   const __half* __restrict__ Bh, const __half* __restrict__ Bl,
                   const float* __restrict__ bias,
                   float* __restrict__ C,
                   const float* __restrict__ v,
                   const float* __restrict__ vp_g,
                   const float* __restrict__ vp_b,
                   __half* __restrict__ vsh, __half* __restrict__ vsl) {
    extern __shared__ char smem[];
    int tid = threadIdx.x;

    if (blockIdx.x >= QA2_BLOCKS) {
        // ---- prep_v path: LN fold + split of 64 v rows, 2 at a time ----
        int row0 = (blockIdx.x - QA2_BLOCKS) * PV_ROWS_PER_BLOCK + (tid >> 5) * 8;
        int lane = tid & 31;
#pragma unroll
        for (int i = 0; i < 8; i += 2)
            ln_split_row2(v, vp_g, vp_b, vsh, vsl, row0 + i, row0 + i + 1, lane);
        return;
    }

    int wid = tid >> 5, lane = tid & 31;
    int warp_m = wid >> 2, warp_n = wid & 3;
    int g = lane >> 2, tig = lane & 3;
    int bm = (blockIdx.x % (BS / 128)) * 128;
    int bn = (blockIdx.x / (BS / 128)) * 128;

    uint32_t sbase = (uint32_t)__cvta_generic_to_shared(smem);
    int lrow = lane & 15;
    int lhk  = ((lane >> 4) & 1) * 8;
    uint32_t a_lane_off = (uint32_t)(((warp_m * 64 + lrow) * ASTRIDE + lhk) * 2);
    int bn_off = (lane & 7) + ((lane >> 4) & 1) * 8;
    int bk_off = ((lane >> 3) & 1) * 8;
    uint32_t b_lane_off = (uint32_t)(((warp_n * 32 + bn_off) * ASTRIDE + bk_off) * 2);

    int arow = tid >> 1, ahalf = tid & 1;
    uint32_t stg_lane = (uint32_t)((arow * ASTRIDE + ahalf * 16) * 2);
    size_t a_src_off = (size_t)(bm + arow) * DIM + ahalf * 16;
    size_t b_src_off = (size_t)(bn + arow) * DIM + ahalf * 16;

    float acc[4][4][4];
#pragma unroll
    for (int i = 0; i < 4; i++)
#pragma unroll
        for (int j = 0; j < 4; j++)
#pragma unroll
            for (int r = 0; r < 4; r++) acc[i][j][r] = 0.f;

    auto issue = [&](int cc) {
        int k0 = cc * BK;
        uint32_t dst = sbase + (uint32_t)(cc & 1) * STAGE_B + stg_lane;
        const __half* sh = Ah + a_src_off + k0;
        const __half* sl = Al + a_src_off + k0;
        CP16(dst, sh); CP16(dst + 16, sh + 8);
        CP16(dst + TILE_B, sl); CP16(dst + TILE_B + 16, sl + 8);
        const __half* th = Bh + b_src_off + k0;
        const __half* tl = Bl + b_src_off + k0;
        uint32_t dstb = dst + 2 * TILE_B;
        CP16(dstb, th); CP16(dstb + 16, th + 8);
        CP16(dstb + TILE_B, tl); CP16(dstb + TILE_B + 16, tl + 8);
        CP_COMMIT();
    };
    auto compute = [&](int st) {
        uint32_t base = sbase + (uint32_t)st * STAGE_B;
#pragma unroll
        for (int ks = 0; ks < 2; ks++) {
            uint32_t koff = (uint32_t)(ks * 16 * 2);
            uint32_t bfr[2][4][2];
#pragma unroll
            for (int sb = 0; sb < 2; sb++) {
                uint32_t bb = base + (2 + sb) * TILE_B + b_lane_off + koff;
#pragma unroll
                for (int p = 0; p < 2; p++) {
                    uint32_t r[4];
                    ldsm_x4(r, bb + (uint32_t)(p * 16 * ASTRIDE * 2));
                    bfr[sb][2 * p][0] = r[0]; bfr[sb][2 * p][1] = r[1];
                    bfr[sb][2 * p + 1][0] = r[2]; bfr[sb][2 * p + 1][1] = r[3];
                }
            }
            uint32_t afr[2][4][4];
#pragma unroll
            for (int sa = 0; sa < 2; sa++) {
                uint32_t ab = base + sa * TILE_B + a_lane_off + koff;
#pragma unroll
                for (int mt = 0; mt < 4; mt++)
                    ldsm_x4(afr[sa][mt], ab + (uint32_t)(mt * 16 * ASTRIDE * 2));
            }
#pragma unroll
            for (int mt = 0; mt < 4; mt++)
#pragma unroll
                for (int nt2 = 0; nt2 < 4; nt2++)
                    mma_f16(acc[mt][nt2], afr[0][mt], bfr[0][nt2]);
#pragma unroll
            for (int mt = 0; mt < 4; mt++)
#pragma unroll
                for (int nt2 = 0; nt2 < 4; nt2++)
                    mma_f16(acc[mt][nt2], afr[0][mt], bfr[1][nt2]);
#pragma unroll
            for (int mt = 0; mt < 4; mt++)
#pragma unroll
                for (int nt2 = 0; nt2 < 4; nt2++)
                    mma_f16(acc[mt][nt2], afr[1][mt], bfr[0][nt2]);
        }
    };

    issue(0);
    CP_WAIT0();
    __syncthreads();

    for (int cc = 0; cc < NCHUNK; cc++) {
        bool more = (cc + 1 < NCHUNK);
        if (more) issue(cc + 1);
        compute(cc & 1);
        if (more) { CP_WAIT0(); __syncthreads(); }
    }

#pragma unroll
    for (int mt = 0; mt < 4; mt++) {
#pragma unroll
        for (int nt2 = 0; nt2 < 4; nt2++) {
            int row = bm + warp_m * 64 + mt * 16 + g;
            int col = bn + warp_n * 32 + nt2 * 8 + tig * 2;
            float2 v0, v1;
            v0.x = gelu_exact(acc[mt][nt2][0] + bias[col]);
            v0.y = gelu_exact(acc[mt][nt2][1] + bias[col + 1]);
            v1.x = gelu_exact(acc[mt][nt2][2] + bias[col]);
            v1.y = gelu_exact(acc[mt][nt2][3] + bias[col + 1]);
            *(float2*)(C + (size_t)row * DIM + col) = v0;
            *(float2*)(C + (size_t)(row + 8) * DIM + col) = v1;
        }
    }
}

// ---------------- fused GEMM1+GEMM3 (M=128, R13 shape) ----------------------
__global__ __launch_bounds__(256, 2)
void fused_gemm_kernel(const __half* __restrict__ Ah, const __half* __restrict__ Al,
                       const __half* __restrict__ Bh, const __half* __restrict__ Bl,
                       const __half* __restrict__ W1h, const __half* __restrict__ W1l,
                       const float* __restrict__ bias,
                       const float* __restrict__ gcol,
                       const float* __restrict__ qa2gate,
                       __half* __restrict__ Yh, __half* __restrict__ Yl,
                       const float* __restrict__ u, const float* __restrict__ wvec,
                       const float* __restrict__ w2, const float* __restrict__ b2,
                       float* __restrict__ logits) {
    extern __shared__ char smem[];
    const unsigned full = 0xffffffffu;
    int tid = threadIdx.x;
    int wid = tid >> 5, lane = tid & 31;
    int warp_m = wid >> 2, warp_n = wid & 3;
    int g = lane >> 2, tig = lane & 3;
    int bm = blockIdx.x * 128;

    uint32_t sbase = (uint32_t)__cvta_generic_to_shared(smem);
    int lrow = lane & 15;
    int lhk  = ((lane >> 4) & 1) * 8;
    uint32_t a_lane_off = (uint32_t)(((warp_m * 64 + lrow) * ASTRIDE + lhk) * 2);
    int bn_off = (lane & 7) + ((lane >> 4) & 1) * 8;
    int bk_off = ((lane >> 3) & 1) * 8;
    uint32_t b_lane_off = (uint32_t)(((warp_n * 32 + bn_off) * ASTRIDE + bk_off) * 2);

    int arow = tid >> 1, ahalf = tid & 1;
    uint32_t stg_lane = (uint32_t)((arow * ASTRIDE + ahalf * 16) * 2);
    size_t a_src_off = (size_t)(bm + arow) * DIM + ahalf * 16;

    float acc[4][4][4];
#pragma unroll
    for (int i = 0; i < 4; i++)
#pragma unroll
        for (int j = 0; j < 4; j++)
#pragma unroll
            for (int r = 0; r < 4; r++) acc[i][j][r] = 0.f;

    float rs[4][2], rss[4][2], rdt[4][2];
#pragma unroll
    for (int i = 0; i < 4; i++) {
        rs[i][0] = rs[i][1] = 0.f;
        rss[i][0] = rss[i][1] = 0.f;
        rdt[i][0] = rdt[i][1] = 0.f;
    }

    auto cp_pair = [&](const __half* Ph, const __half* Pl, size_t off,
                       int cc, int slot) {
        uint32_t dst = sbase + (uint32_t)(cc & 1) * STAGE_B
                     + (uint32_t)slot * (2 * TILE_B) + stg_lane;
        CP16(dst, Ph + off); CP16(dst + 16, Ph + off + 8);
        CP16(dst + TILE_B, Pl + off); CP16(dst + TILE_B + 16, Pl + off + 8);
    };
    auto compute = [&](int st) {
        uint32_t base = sbase + (uint32_t)st * STAGE_B;
#pragma unroll
        for (int ks = 0; ks < 2; ks++) {
            uint32_t koff = (uint32_t)(ks * 16 * 2);
            uint32_t bfr[2][4][2];
#pragma unroll
            for (int sb = 0; sb < 2; sb++) {
                uint32_t bb = base + (2 + sb) * TILE_B + b_lane_off + koff;
#pragma unroll
                for (int p = 0; p < 2; p++) {
                    uint32_t r[4];
                    ldsm_x4(r, bb + (uint32_t)(p * 16 * ASTRIDE * 2));
                    bfr[sb][2 * p][0] = r[0]; bfr[sb][2 * p][1] = r[1];
                    bfr[sb][2 * p + 1][0] = r[2]; bfr[sb][2 * p + 1][1] = r[3];
                }
            }
            uint32_t afr[2][4][4];
#pragma unroll
            for (int sa = 0; sa < 2; sa++) {
                uint32_t ab = base + sa * TILE_B + a_lane_off + koff;
#pragma unroll
                for (int mt = 0; mt < 4; mt++)
                    ldsm_x4(afr[sa][mt], ab + (uint32_t)(mt * 16 * ASTRIDE * 2));
            }
#pragma unroll
            for (int mt = 0; mt < 4; mt++)
#pragma unroll
                for (int nt2 = 0; nt2 < 4; nt2++)
                    mma_f16(acc[mt][nt2], afr[0][mt], bfr[0][nt2]);
#pragma unroll
            for (int mt = 0; mt < 4; mt++)
#pragma unroll
                for (int nt2 = 0; nt2 < 4; nt2++)
                    mma_f16(acc[mt][nt2], afr[0][mt], bfr[1][nt2]);
#pragma unroll
            for (int mt = 0; mt < 4; mt++)
#pragma unroll
                for (int nt2 = 0; nt2 < 4; nt2++)
                    mma_f16(acc[mt][nt2], afr[1][mt], bfr[0][nt2]);
        }
    };

    // ================== PHASE 1: v2 / y / gate stats ==================
    {
        const int NCH = NT1 * NCHUNK;
        auto issue = [&](int cc) {
            int k0 = (cc % NCHUNK) * BK;
            int nt = cc / NCHUNK;
            cp_pair(Ah, Al, a_src_off + k0, cc, 0);
            cp_pair(Bh, Bl, (size_t)(nt * 128 + arow) * DIM + k0 + ahalf * 16, cc, 1);
            CP_COMMIT();
        };
        issue(0); CP_WAIT0(); __syncthreads();
        for (int cc = 0; cc < NCH; cc++) {
            bool more = (cc + 1 < NCH);
            if (more) issue(cc + 1);
            compute(cc & 1);
            if (((cc + 1) % NCHUNK) == 0) {
                int bn = (cc / NCHUNK) * 128;
#pragma unroll
                for (int mt = 0; mt < 4; mt++) {
#pragma unroll
                    for (int nt2 = 0; nt2 < 4; nt2++) {
                        int row = bm + warp_m * 64 + mt * 16 + g;
                        int col = bn + warp_n * 32 + nt2 * 8 + tig * 2;
                        float2 v0, v1;
                        v0.x = gelu_exact(acc[mt][nt2][0] + bias[col]);
                        v0.y = gelu_exact(acc[mt][nt2][1] + bias[col + 1]);
                        v1.x = gelu_exact(acc[mt][nt2][2] + bias[col]);
                        v1.y = gelu_exact(acc[mt][nt2][3] + bias[col + 1]);
                        float2 g2 = *(const float2*)(gcol + col);
                        float y00 = v0.x * g2.x, y01 = v0.y * g2.y;
                        float y10 = v1.x * g2.x, y11 = v1.y * g2.y;
                        __half2 h0 = __floats2half2_rn(y00, y01);
                        __half2 h1 = __floats2half2_rn(y10, y11);
                        __half2 l0 = __floats2half2_rn(y00 - __low2float(h0),
                                                       y01 - __high2float(h0));
                        __half2 l1 = __floats2half2_rn(y10 - __low2float(h1),
                                                       y11 - __high2float(h1));
                        size_t o0 = (size_t)row * DIM + col;
                        size_t o1 = (size_t)(row + 8) * DIM + col;
                        *(uint32_t*)(Yh + o0) = *(uint32_t*)&h0;
                        *(uint32_t*)(Yh + o1) = *(uint32_t*)&h1;
                        *(uint32_t*)(Yl + o0) = *(uint32_t*)&l0;
                        *(uint32_t*)(Yl + o1) = *(uint32_t*)&l1;
                        int b0 = row >> 5;
                        float2 q = *(const float2*)(qa2gate + (size_t)b0 * DIM + col);
                        rs[mt][0]  += v0.x + v0.y;
                        rss[mt][0] += v0.x * v0.x + v0.y * v0.y;
                        rdt[mt][0] += v0.x * q.x + v0.y * q.y;
                        rs[mt][1]  += v1.x + v1.y;
                        rss[mt][1] += v1.x * v1.x + v1.y * v1.y;
                        rdt[mt][1] += v1.x * q.x + v1.y * q.y;
                        acc[mt][nt2][0] = 0.f; acc[mt][nt2][1] = 0.f;
                        acc[mt][nt2][2] = 0.f; acc[mt][nt2][3] = 0.f;
                    }
                }
            }
            if (more) { CP_WAIT0(); __syncthreads(); }
        }
    }

    // ---- gate/LN-fold stats -> smem alpha/m2 ----
    float* sal = (float*)(smem + SAL_OFF);
    float* sm2 = sal + 128;
    {
#pragma unroll
        for (int off = 1; off <= 2; off <<= 1) {
#pragma unroll
            for (int mt = 0; mt < 4; mt++) {
#pragma unroll
                for (int h = 0; h < 2; h++) {
                    rs[mt][h]  += __shfl_xor_sync(full, rs[mt][h],  off);
                    rss[mt][h] += __shfl_xor_sync(full, rss[mt][h], off);
                    rdt[mt][h] += __shfl_xor_sync(full, rdt[mt][h], off);
                }
            }
        }
        float* sred = (float*)(smem + SRED_OFF);
        __syncthreads();   // also orders phase-1 Y stores before phase-2 reads
        if (tig == 0) {
#pragma unroll
            for (int mt = 0; mt < 4; mt++) {
#pragma unroll
                for (int h = 0; h < 2; h++) {
                    int r = warp_m * 64 + mt * 16 + g + h * 8;
                    sred[0 * 512 + warp_n * 128 + r] = rs[mt][h];
                    sred[1 * 512 + warp_n * 128 + r] = rss[mt][h];
                    sred[2 * 512 + warp_n * 128 + r] = rdt[mt][h];
                }
            }
        }
        __syncthreads();
        if (tid < 128) {
            float s = 0.f, ss2 = 0.f, dt = 0.f;
#pragma unroll
            for (int w = 0; w < 4; w++) {
                s   += sred[0 * 512 + w * 128 + tid];
                ss2 += sred[1 * 512 + w * 128 + tid];
                dt  += sred[2 * 512 + w * 128 + tid];
            }
            float m = s / DIM;
            float var = fmaxf(ss2 / DIM - m * m, 0.f);
            float gate = tanhf(dt);
            sm2[tid] = m;
            sal[tid] = gate * rsqrtf(gate * gate * var + LN_EPS);
        }
        __syncthreads();
    }

    // per-row constants for phase 2
    float alp[4][2], mm[4][2];
#pragma unroll
    for (int mt = 0; mt < 4; mt++) {
        int r0 = warp_m * 64 + mt * 16 + g;
        alp[mt][0] = sal[r0];     mm[mt][0] = sm2[r0];
        alp[mt][1] = sal[r0 + 8]; mm[mt][1] = sm2[r0 + 8];
    }

    // ================== PHASE 2: logits ==================
    float dotacc = 0.f;
    {
        const int NCH = NT2 * NCHUNK;
        auto issue = [&](int cc) {
            int k0 = (cc % NCHUNK) * BK;
            int nt = cc / NCHUNK;
            cp_pair(Yh, Yl, a_src_off + k0, cc, 0);
            cp_pair(W1h, W1l, (size_t)(nt * 128 + arow) * DIM + k0 + ahalf * 16, cc, 1);
            CP_COMMIT();
        };
        issue(0); CP_WAIT0(); __syncthreads();
        for (int cc = 0; cc < NCH; cc++) {
            bool more = (cc + 1 < NCH);
            if (more) issue(cc + 1);
            compute(cc & 1);
            if (((cc + 1) % NCHUNK) == 0) {
                int bn = (cc / NCHUNK) * 128;
                float part[4][2];
#pragma unroll
                for (int mt = 0; mt < 4; mt++) { part[mt][0] = 0.f; part[mt][1] = 0.f; }
#pragma unroll
                for (int mt = 0; mt < 4; mt++) {
#pragma unroll
                    for (int nt2 = 0; nt2 < 4; nt2++) {
                        int n0 = bn + warp_n * 32 + nt2 * 8 + tig * 2;
                        float u0 = u[n0], u1 = u[n0 + 1];
                        float wv0 = wvec[n0], wv1 = wvec[n0 + 1];
                        float w20 = w2[n0], w21 = w2[n0 + 1];
                        float h00 = alp[mt][0] * (acc[mt][nt2][0] - mm[mt][0] * u0) + wv0;
                        float h01 = alp[mt][0] * (acc[mt][nt2][1] - mm[mt][0] * u1) + wv1;
                        float h10 = alp[mt][1] * (acc[mt][nt2][2] - mm[mt][1] * u0) + wv0;
                        float h11 = alp[mt][1] * (acc[mt][nt2][3] - mm[mt][1] * u1) + wv1;
                        part[mt][0] += gelu_exact(h00) * w20 + gelu_exact(h01) * w21;
                        part[mt][1] += gelu_exact(h10) * w20 + gelu_exact(h11) * w21;
                        acc[mt][nt2][0] = 0.f; acc[mt][nt2][1] = 0.f;
                        acc[mt][nt2][2] = 0.f; acc[mt][nt2][3] = 0.f;
                    }
                }
#pragma unroll
                for (int off = 1; off <= 2; off <<= 1) {
#pragma unroll
                    for (int mt = 0; mt < 4; mt++) {
                        part[mt][0] += __shfl_xor_sync(full, part[mt][0], off);
                        part[mt][1] += __shfl_xor_sync(full, part[mt][1], off);
                    }
                }
                float* sr = (float*)(smem + SRED_OFF);
                if (tig == 0) {
#pragma unroll
                    for (int mt = 0; mt < 4; mt++) {
                        int r = warp_m * 64 + mt * 16 + g;
                        sr[warp_n * 128 + r] = part[mt][0];
                        sr[warp_n * 128 + r + 8] = part[mt][1];
                    }
                }
                __syncthreads();
                if (tid < 128)
                    dotacc += ((sr[tid] + sr[128 + tid]) + (sr[256 + tid] + sr[384 + tid]));
                __syncthreads();
            }
            if (more) { CP_WAIT0(); __syncthreads(); }
        }
    }

    if (tid < 128)
        logits[bm + tid] = dotacc + b2[0];
}

// ---------------- finalize: shared gaussian kern, warp-parallel search ------
#define OFF_GS     0
#define OFF_MAXIDX (BS * LEN)
#define OFF_START  (BS * LEN + BS * 2)
#define OFF_END    (BS * LEN + BS * 3)
#define OFF_MASK   (BS * LEN + BS * 4)
#define OFF_ORIKEY (BS * LEN * 2 + BS * 4)

__global__ void finalize_kernel(const float* __restrict__ sigma_ptr,
                                float* __restrict__ out) {
    const unsigned full = 0xffffffffu;
    int tid = threadIdx.x;
    int warp = tid >> 5, lane = tid & 31;

    __shared__ double kraw[5];
    __shared__ double kern_s[5];
    if (tid < 5) {
        double sigma = (double)(*sigma_ptr);
        double x = (double)(tid - 2) / sigma;
        kraw[tid] = exp(-0.5 * x * x);
    }
    __syncthreads();
    if (tid < 5) {
        double ks = kraw[0] + kraw[1] + kraw[2] + kraw[3] + kraw[4];
        kern_s[tid] = kraw[tid] / ks;
    }
    __syncthreads();
    double kern[5];
#pragma unroll
    for (int j = 0; j < 5; j++) kern[j] = kern_s[j];

    int b = blockIdx.x * 8 + warp;
    float logit_f = g_logits[b * LEN + lane];
    double logit = (double)logit_f;

    double m = logit;
    for (int o = 16; o; o >>= 1) m = fmax(m, __shfl_xor_sync(full, m, o));
    double e = exp(logit - m);
    double s = e;
    for (int o = 16; o; o >>= 1) s += __shfl_xor_sync(full, s, o);
    double kp = e / s;

    double sm = 0.0;
#pragma unroll
    for (int j = 0; j < 5; j++) {
        int src = lane + j - 2;
        double v = __shfl_sync(full, kp, src & 31);
        if (src >= 0 && src < LEN) sm += kern[j] * v;
    }

    double mg = sm;
    for (int o = 16; o; o >>= 1) mg = fmax(mg, __shfl_xor_sync(full, mg, o));
    double eg = exp(sm - mg);
    double sg = eg;
    for (int o = 16; o; o >>= 1) sg += __shfl_xor_sync(full, sg, o);
    double gs = eg / sg;

    double bv = gs; int bi = lane;
    for (int o = 16; o; o >>= 1) {
        double ov = __shfl_xor_sync(full, bv, o);
        int    oi = __shfl_xor_sync(full, bi, o);
        if (ov > bv || (ov == bv && oi < bi)) { bv = ov; bi = oi; }
    }
    int amax = bi;

    double cs = gs;
#pragma unroll
    for (int off = 1; off < 32; off <<= 1) {
        double t = __shfl_up_sync(full, cs, off);
        if (lane >= off) cs += t;
    }

    double bestv = -INFINITY;
    int bestc = 1 << 20;
#pragma unroll
    for (int r = 0; r < 3; r++) {
        int c = lane + r * 32;
        int w, st;
        if (c < 32)      { w = 1; st = c; }
        else if (c < 62) { w = 3; st = c - 32; }
        else             { w = 5; st = c - 62; }
        bool valid = (c < 90);
        double hi = __shfl_sync(full, cs, (st + w - 1) & 31);
        double lo = __shfl_sync(full, cs, (st - 1) & 31);
        double sum = hi - ((st > 0) ? lo : 0.0);
        bool contains = (amax >= st) && (amax < st + w);
        double val = (valid && contains) ? sum : -INFINITY;
        if (val > bestv || (val == bestv && c < bestc)) { bestv = val; bestc = c; }
    }
    for (int off = 16; off; off >>= 1) {
        double ov = __shfl_xor_sync(full, bestv, off);
        int    oc = __shfl_xor_sync(full, bestc, off);
        if (ov > bestv || (ov == bestv && oc < bestc)) { bestv = ov; bestc = oc; }
    }
    int s0, e0;
    {
        int c = bestc, w, st;
        if (c < 32)      { w = 1; st = c; }
        else if (c < 62) { w = 3; st = c - 32; }
        else             { w = 5; st = c - 62; }
        s0 = st; e0 = st + w;
    }

    out[OFF_GS + b * LEN + lane] = (float)gs;
    if (lane == 0) {
        out[OFF_MAXIDX + b * 2 + 0] = (float)s0;
        out[OFF_MAXIDX + b * 2 + 1] = (float)e0;
        out[OFF_START + b] = (float)s0 / 31.0f;
        out[OFF_END + b]   = (float)e0 / 31.0f;
    }
    out[OFF_MASK + b * LEN + lane] = (lane >= s0 && lane <= e0) ? 1.f : 0.f;
    out[OFF_ORIKEY + b * LEN + lane] = logit_f;
}

// ---------------- launch ----------------------------------------------------
extern "C" void kernel_launch(void* const* d_in, const int* in_sizes, int n_in,
                              void* d_out, int out_size) {
    const float* v       = (const float*)d_in[0];
    const float* qa      = (const float*)d_in[1];
    const float* vp_g    = (const float*)d_in[2];
    const float* vp_b    = (const float*)d_in[3];
    const float* vp_W    = (const float*)d_in[4];
    const float* vp_bias = (const float*)d_in[5];
    const float* qp_g    = (const float*)d_in[6];
    const float* qp_b    = (const float*)d_in[7];
    const float* qp_W    = (const float*)d_in[8];
    const float* qp_bias = (const float*)d_in[9];
    const float* gr_g    = (const float*)d_in[10];
    const float* gr_b    = (const float*)d_in[11];
    const float* gr_W1   = (const float*)d_in[12];
    const float* gr_b1   = (const float*)d_in[13];
    const float* gr_W2   = (const float*)d_in[14];
    const float* gr_b2   = (const float*)d_in[15];
    const float* sigma   = (const float*)d_in[16];
    float* out = (float*)d_out;

    void *p_qa2, *p_lg, *p_u, *p_w;
    void *p_vs, *p_qs, *p_y, *p_vpw, *p_qpw, *p_w1;
    cudaGetSymbolAddress(&p_qa2, g_qa2);
    cudaGetSymbolAddress(&p_lg,  g_logits);
    cudaGetSymbolAddress(&p_u,   g_u);
    cudaGetSymbolAddress(&p_w,   g_w);
    cudaGetSymbolAddress(&p_vs,  g_vs);
    cudaGetSymbolAddress(&p_qs,  g_qs);
    cudaGetSymbolAddress(&p_y,   g_y);
    cudaGetSymbolAddress(&p_vpw, g_vpW_s);
    cudaGetSymbolAddress(&p_qpw, g_qpW_s);
    cudaGetSymbolAddress(&p_w1,  g_grW1_s);

    __half* vs  = (__half*)p_vs;
    __half* qs  = (__half*)p_qs;
    __half* yy  = (__half*)p_y;
    __half* vpw = (__half*)p_vpw;
    __half* qpw = (__half*)p_qpw;
    __half* w1s = (__half*)p_w1;
    const size_t VN = (size_t)ROWS * DIM;
    const size_t QN = (size_t)BS * DIM;

    cudaFuncSetAttribute((const void*)stage2_kernel,
                         cudaFuncAttributeMaxDynamicSharedMemorySize, SMEM_DYN);
    cudaFuncSetAttribute((const void*)fused_gemm_kernel,
                         cudaFuncAttributeMaxDynamicSharedMemorySize, SMEM_DYN);

    // [1] transposes + LN-split(qa) + u/w (all independent, one launch)
    prep_stage1<<<S1_BLOCKS, 256>>>(
        vp_W, qp_W, gr_W1, vpw, qpw, w1s,
        qa, qp_g, qp_b, qs, qs + QN,
        gr_g, gr_b, gr_b1, (float*)p_u, (float*)p_w);

    // [2] qa2 GEMM tiles + LN-split(v) co-scheduled (tensor + memory overlap)
    stage2_kernel<<<S2_BLOCKS, 256, SMEM_DYN>>>(
        qs, qs + QN, qpw, qpw + (size_t)DIM * DIM, qp_bias, (float*)p_qa2,
        v, vp_g, vp_b, vs, vs + VN);

    // [3] fused GEMM1+GEMM3 (M=128, proven R13 shape)
    fused_gemm_kernel<<<ROWS / 128, 256, SMEM_DYN>>>(
        vs, vs + VN, vpw, vpw + (size_t)DIM * DIM,
        w1s, w1s + (size_t)HID * DIM,
        vp_bias, gr_g, (const float*)p_qa2,
        yy, yy + VN,
        (const float*)p_u, (const float*)p_w,
        gr_W2, gr_b2, (float*)p_lg);

    // [4] finalize
    finalize_kernel<<<BS / 8, 256>>>(sigma, out);
}

// round 16
// speedup vs baseline: 1.0480x; 1.0291x over previous
#include <cuda_runtime.h>
#include <cuda_fp16.h>
#include <math.h>
#include <stdint.h>

#define BS   4096
#define LEN  32
#define DIM  768
#define HID  384
#define ROWS (BS * LEN)          // 131072
#define LN_EPS 1e-5f

// ---- mma tiling ----
#define BK 32
#define NCHUNK (DIM / BK)        // 24
#define NT1 (DIM / 128)          // 6
#define NT2 (HID / 128)          // 3
#define ASTRIDE 40               // fp16 elems per smem row (80B, 16B-divisible)
#define TILE_B (128 * ASTRIDE * 2)   // 10240 bytes per split tile
#define STAGE_B (4 * TILE_B)         // A_hi,A_lo,B_hi,B_lo = 40960
#define SRED_OFF (2 * STAGE_B)       // 81920
#define SAL_OFF  (SRED_OFF + 3 * 512 * 4)   // 88064
#define SMEM_DYN (SAL_OFF + 2 * 128 * 4)    // 89088  (x2 CTAs <= 228KB)

// stage-1 combined grid layout
#define TR_BLOCKS   (24 * 24 * 3)            // 1728 transpose tiles
#define QAP_BLOCKS  (BS / 8)                 // 512 qa LN-split blocks
#define UW_BLOCKS   (HID / 8)                // 48 u/w blocks
#define S1_BLOCKS   (TR_BLOCKS + QAP_BLOCKS + UW_BLOCKS)
// stage-2 combined grid layout
#define QA2_BLOCKS  ((BS / 128) * (DIM / 128))   // 192
#define PV_ROWS_PER_BLOCK 64
#define PV_BLOCKS   (ROWS / PV_ROWS_PER_BLOCK)   // 2048
#define S2_BLOCKS   (QA2_BLOCKS + PV_BLOCKS)

// ---------------- scratch (device globals; no runtime allocation) ----------
__device__ float g_qa2[BS * DIM];
__device__ float g_logits[ROWS];
__device__ float g_u[HID];
__device__ float g_w[HID];
// pre-split operands (hi at 0, lo at +count)
__device__ __align__(16) __half g_vs[2 * (size_t)ROWS * DIM];   // LN(v) split
__device__ __align__(16) __half g_qs[2 * (size_t)BS * DIM];     // LN(qa) split
__device__ __align__(16) __half g_y [2 * (size_t)ROWS * DIM];   // v2*g split
// transposed+split weights, [split][n][k]
__device__ __align__(16) __half g_vpW_s[2 * DIM * DIM];
__device__ __align__(16) __half g_qpW_s[2 * DIM * DIM];
__device__ __align__(16) __half g_grW1_s[2 * HID * DIM];

__device__ __forceinline__ float gelu_exact(float x) {
    return 0.5f * x * (1.0f + erff(x * 0.70710678118654752440f));
}
__device__ __forceinline__ void mma_f16(float* d, const uint32_t* a, const uint32_t* b) {
    asm volatile(
        "mma.sync.aligned.m16n8k16.row.col.f32.f16.f16.f32 "
        "{%0,%1,%2,%3}, {%4,%5,%6,%7}, {%8,%9}, {%0,%1,%2,%3};"
        : "+f"(d[0]), "+f"(d[1]), "+f"(d[2]), "+f"(d[3])
        : "r"(a[0]), "r"(a[1]), "r"(a[2]), "r"(a[3]), "r"(b[0]), "r"(b[1]));
}
__device__ __forceinline__ void ldsm_x4(uint32_t* r, uint32_t addr) {
    asm volatile("ldmatrix.sync.aligned.m8n8.x4.shared.b16 {%0,%1,%2,%3}, [%4];"
                 : "=r"(r[0]), "=r"(r[1]), "=r"(r[2]), "=r"(r[3]) : "r"(addr));
}
// L2-direct (bypass L1): GEMM staging never re-reads through L1
#define CP16(dst, src) \
    asm volatile("cp.async.cg.shared.global [%0], [%1], 16;" :: "r"(dst), "l"(src))
#define CP_COMMIT() asm volatile("cp.async.commit_group;")
#define CP_WAIT0()  asm volatile("cp.async.wait_group 0;")

// ---------------- device helper: LN fold + fp16 split of one row ------------
__device__ __forceinline__ void ln_split_row(const float* __restrict__ X,
                                             const float* __restrict__ lng,
                                             const float* __restrict__ lnb,
                                             __half* __restrict__ Sh,
                                             __half* __restrict__ Sl,
                                             int row, int lane) {
    const float* x = X + (size_t)row * DIM;
    float4 xv[6];
    float s = 0.f, ss = 0.f;
#pragma unroll
    for (int i = 0; i < 6; i++) {
        xv[i] = *(const float4*)(x + i * 128 + lane * 4);
        s += xv[i].x + xv[i].y + xv[i].z + xv[i].w;
        ss = fmaf(xv[i].x, xv[i].x, ss);
        ss = fmaf(xv[i].y, xv[i].y, ss);
        ss = fmaf(xv[i].z, xv[i].z, ss);
        ss = fmaf(xv[i].w, xv[i].w, ss);
    }
    for (int o = 16; o; o >>= 1) {
        s  += __shfl_xor_sync(0xffffffffu, s,  o);
        ss += __shfl_xor_sync(0xffffffffu, ss, o);
    }
    float m = s / DIM;
    float rstd = rsqrtf(fmaxf(ss / DIM - m * m, 0.f) + LN_EPS);
#pragma unroll
    for (int i = 0; i < 6; i++) {
        int k = i * 128 + lane * 4;
        float4 g4 = *(const float4*)(lng + k);
        float4 b4 = *(const float4*)(lnb + k);
        float x0 = fmaf(xv[i].x - m, rstd * g4.x, b4.x);
        float x1 = fmaf(xv[i].y - m, rstd * g4.y, b4.y);
        float x2 = fmaf(xv[i].z - m, rstd * g4.z, b4.z);
        float x3 = fmaf(xv[i].w - m, rstd * g4.w, b4.w);
        __half2 h01 = __floats2half2_rn(x0, x1);
        __half2 h23 = __floats2half2_rn(x2, x3);
        float r0 = x0 - __low2float(h01), r1 = x1 - __high2float(h01);
        float r2 = x2 - __low2float(h23), r3 = x3 - __high2float(h23);
        __half2 l01 = __floats2half2_rn(r0, r1);
        __half2 l23 = __floats2half2_rn(r2, r3);
        size_t off = (size_t)row * DIM + k;
        *(uint2*)(Sh + off) = make_uint2(*(uint32_t*)&h01, *(uint32_t*)&h23);
        *(uint2*)(Sl + off) = make_uint2(*(uint32_t*)&l01, *(uint32_t*)&l23);
    }
}

// ---------------- two rows concurrently (doubled MLP; per-row math identical)
__device__ __forceinline__ void ln_split_row2(const float* __restrict__ X,
                                              const float* __restrict__ lng,
                                              const float* __restrict__ lnb,
                                              __half* __restrict__ Sh,
                                              __half* __restrict__ Sl,
                                              int rowA, int rowB, int lane) {
    const float* xa = X + (size_t)rowA * DIM;
    const float* xb = X + (size_t)rowB * DIM;
    float4 va[6], vb[6];
#pragma unroll
    for (int i = 0; i < 6; i++) {
        va[i] = *(const float4*)(xa + i * 128 + lane * 4);
        vb[i] = *(const float4*)(xb + i * 128 + lane * 4);
    }
    float sa = 0.f, ssa = 0.f, sb = 0.f, ssb = 0.f;
#pragma unroll
    for (int i = 0; i < 6; i++) {
        sa += va[i].x + va[i].y + va[i].z + va[i].w;
        ssa = fmaf(va[i].x, va[i].x, ssa);
        ssa = fmaf(va[i].y, va[i].y, ssa);
        ssa = fmaf(va[i].z, va[i].z, ssa);
        ssa = fmaf(va[i].w, va[i].w, ssa);
        sb += vb[i].x + vb[i].y + vb[i].z + vb[i].w;
        ssb = fmaf(vb[i].x, vb[i].x, ssb);
        ssb = fmaf(vb[i].y, vb[i].y, ssb);
        ssb = fmaf(vb[i].z, vb[i].z, ssb);
        ssb = fmaf(vb[i].w, vb[i].w, ssb);
    }
    for (int o = 16; o; o >>= 1) {
        sa  += __shfl_xor_sync(0xffffffffu, sa,  o);
        ssa += __shfl_xor_sync(0xffffffffu, ssa, o);
        sb  += __shfl_xor_sync(0xffffffffu, sb,  o);
        ssb += __shfl_xor_sync(0xffffffffu, ssb, o);
    }
    float ma = sa / DIM;
    float ra = rsqrtf(fmaxf(ssa / DIM - ma * ma, 0.f) + LN_EPS);
    float mb = sb / DIM;
    float rb = rsqrtf(fmaxf(ssb / DIM - mb * mb, 0.f) + LN_EPS);
#pragma unroll
    for (int i = 0; i < 6; i++) {
        int k = i * 128 + lane * 4;
        float4 g4 = *(const float4*)(lng + k);
        float4 b4 = *(const float4*)(lnb + k);
        {
            float x0 = fmaf(va[i].x - ma, ra * g4.x, b4.x);
            float x1 = fmaf(va[i].y - ma, ra * g4.y, b4.y);
            float x2 = fmaf(va[i].z - ma, ra * g4.z, b4.z);
            float x3 = fmaf(va[i].w - ma, ra * g4.w, b4.w);
            __half2 h01 = __floats2half2_rn(x0, x1);
            __half2 h23 = __floats2half2_rn(x2, x3);
            float r0 = x0 - __low2float(h01), r1 = x1 - __high2float(h01);
            float r2 = x2 - __low2float(h23), r3 = x3 - __high2float(h23);
            __half2 l01 = __floats2half2_rn(r0, r1);
            __half2 l23 = __floats2half2_rn(r2, r3);
            size_t off = (size_t)rowA * DIM + k;
            *(uint2*)(Sh + off) = make_uint2(*(uint32_t*)&h01, *(uint32_t*)&h23);
            *(uint2*)(Sl + off) = make_uint2(*(uint32_t*)&l01, *(uint32_t*)&l23);
        }
        {
            float x0 = fmaf(vb[i].x - mb, rb * g4.x, b4.x);
            float x1 = fmaf(vb[i].y - mb, rb * g4.y, b4.y);
            float x2 = fmaf(vb[i].z - mb, rb * g4.z, b4.z);
            float x3 = fmaf(vb[i].w - mb, rb * g4.w, b4.w);
            __half2 h01 = __floats2half2_rn(x0, x1);
            __half2 h23 = __floats2half2_rn(x2, x3);
            float r0 = x0 - __low2float(h01), r1 = x1 - __high2float(h01);
            float r2 = x2 - __low2float(h23), r3 = x3 - __high2float(h23);
            __half2 l01 = __floats2half2_rn(r0, r1);
            __half2 l23 = __floats2half2_rn(r2, r3);
            size_t off = (size_t)rowB * DIM + k;
            *(uint2*)(Sh + off) = make_uint2(*(uint32_t*)&h01, *(uint32_t*)&h23);
            *(uint2*)(Sl + off) = make_uint2(*(uint32_t*)&l01, *(uint32_t*)&l23);
        }
    }
}

// ---------------- stage 1: transposes + LN-split(qa) + u/w ------------------
__global__ void prep_stage1(const float* __restrict__ vpW,
                            const float* __restrict__ qpW,
                            const float* __restrict__ W1,
                            __half* __restrict__ vout,
                            __half* __restrict__ qout,
                            __half* __restrict__ w1out,
                            const float* __restrict__ qa,
                            const float* __restrict__ qp_g,
                            const float* __restrict__ qp_b,
                            __half* __restrict__ qsh, __half* __restrict__ qsl,
                            const float* __restrict__ gr_g,
                            const float* __restrict__ gr_b,
                            const float* __restrict__ gr_b1,
                            float* __restrict__ u, float* __restrict__ w) {
    int b = blockIdx.x;
    int tid = threadIdx.x;
    if (b < TR_BLOCKS) {
        int z = b / 576, rem = b % 576;
        const float* W; __half* Ws; int N;
        if (z == 0)      { W = vpW; Ws = vout;  N = DIM; }
        else if (z == 1) { W = qpW; Ws = qout;  N = DIM; }
        else             { W = W1;  Ws = w1out; N = HID; }
        int n0 = (rem % 24) * 32, k0 = (rem / 24) * 32;
        if (n0 >= N) return;
        __shared__ float t[32][33];
        int tx = tid & 31, ty = tid >> 5;   // 32 x 8
#pragma unroll
        for (int i = 0; i < 4; i++)
            t[ty + i * 8][tx] = W[(size_t)(k0 + ty + i * 8) * N + n0 + tx];
        __syncthreads();
        size_t ss = (size_t)N * DIM;
#pragma unroll
        for (int i = 0; i < 4; i++) {
            int n = n0 + ty + i * 8;
            float x = t[tx][ty + i * 8];
            __half hb = __float2half_rn(x);
            float r = x - __half2float(hb);
            __half lb = __float2half_rn(r);
            size_t o = (size_t)n * DIM + k0 + tx;
            Ws[o] = hb; Ws[ss + o] = lb;
        }
    } else if (b < TR_BLOCKS + QAP_BLOCKS) {
        int row = (b - TR_BLOCKS) * 8 + (tid >> 5);
        ln_split_row(qa, qp_g, qp_b, qsh, qsl, row, tid & 31);
    } else {
        int n = (b - TR_BLOCKS - QAP_BLOCKS) * 8 + (tid >> 5);
        if (n >= HID) return;
        int lane = tid & 31;
        float su = 0.f, sw = 0.f;
        for (int k = lane; k < DIM; k += 32) {
            float wv = W1[(size_t)k * HID + n];
            su = fmaf(gr_g[k], wv, su);
            sw = fmaf(gr_b[k], wv, sw);
        }
        for (int o = 16; o; o >>= 1) {
            su += __shfl_xor_sync(0xffffffffu, su, o);
            sw += __shfl_xor_sync(0xffffffffu, sw, o);
        }
        if (lane == 0) { u[n] = su; w[n] = sw + gr_b1[n]; }
    }
}

// ---------------- stage 2: qa2 GEMM tiles + LN-split(v), co-scheduled -------
__global__ __launch_bounds__(256, 2)
void stage2_kernel(const __half* __restrict__ Ah, const __half* __restrict__ Al,
                   const __half* __restrict__ Bh, const __half* __restrict__ Bl,
                   const float* __restrict__ bias,
                   float* __restrict__ C,
                   const float* __restrict__ v,
                   const float* __restrict__ vp_g,
                   const float* __restrict__ vp_b,
                   __half* __restrict__ vsh, __half* __restrict__ vsl) {
    extern __shared__ char smem[];
    int tid = threadIdx.x;

    if (blockIdx.x >= QA2_BLOCKS) {
        // ---- prep_v path: LN fold + split of 64 v rows, 2 at a time ----
        int row0 = (blockIdx.x - QA2_BLOCKS) * PV_ROWS_PER_BLOCK + (tid >> 5) * 8;
        int lane = tid & 31;
#pragma unroll
        for (int i = 0; i < 8; i += 2)
            ln_split_row2(v, vp_g, vp_b, vsh, vsl, row0 + i, row0 + i + 1, lane);
        return;
    }

    int wid = tid >> 5, lane = tid & 31;
    int warp_m = wid >> 2, warp_n = wid & 3;
    int g = lane >> 2, tig = lane & 3;
    int bm = (blockIdx.x % (BS / 128)) * 128;
    int bn = (blockIdx.x / (BS / 128)) * 128;

    uint32_t sbase = (uint32_t)__cvta_generic_to_shared(smem);
    int lrow = lane & 15;
    int lhk  = ((lane >> 4) & 1) * 8;
    uint32_t a_lane_off = (uint32_t)(((warp_m * 64 + lrow) * ASTRIDE + lhk) * 2);
    int bn_off = (lane & 7) + ((lane >> 4) & 1) * 8;
    int bk_off = ((lane >> 3) & 1) * 8;
    uint32_t b_lane_off = (uint32_t)(((warp_n * 32 + bn_off) * ASTRIDE + bk_off) * 2);

    int arow = tid >> 1, ahalf = tid & 1;
    uint32_t stg_lane = (uint32_t)((arow * ASTRIDE + ahalf * 16) * 2);
    size_t a_src_off = (size_t)(bm + arow) * DIM + ahalf * 16;
    size_t b_src_off = (size_t)(bn + arow) * DIM + ahalf * 16;

    float acc[4][4][4];
#pragma unroll
    for (int i = 0; i < 4; i++)
#pragma unroll
        for (int j = 0; j < 4; j++)
#pragma unroll
            for (int r = 0; r < 4; r++) acc[i][j][r] = 0.f;

    auto issue = [&](int cc) {
        int k0 = cc * BK;
        uint32_t dst = sbase + (uint32_t)(cc & 1) * STAGE_B + stg_lane;
        const __half* sh = Ah + a_src_off + k0;
        const __half* sl = Al + a_src_off + k0;
        CP16(dst, sh); CP16(dst + 16, sh + 8);
        CP16(dst + TILE_B, sl); CP16(dst + TILE_B + 16, sl + 8);
        const __half* th = Bh + b_src_off + k0;
        const __half* tl = Bl + b_src_off + k0;
        uint32_t dstb = dst + 2 * TILE_B;
        CP16(dstb, th); CP16(dstb + 16, th + 8);
        CP16(dstb + TILE_B, tl); CP16(dstb + TILE_B + 16, tl + 8);
        CP_COMMIT();
    };
    auto compute = [&](int st) {
        uint32_t base = sbase + (uint32_t)st * STAGE_B;
#pragma unroll
        for (int ks = 0; ks < 2; ks++) {
            uint32_t koff = (uint32_t)(ks * 16 * 2);
            uint32_t bfr[2][4][2];
#pragma unroll
            for (int sb = 0; sb < 2; sb++) {
                uint32_t bb = base + (2 + sb) * TILE_B + b_lane_off + koff;
#pragma unroll
                for (int p = 0; p < 2; p++) {
                    uint32_t r[4];
                    ldsm_x4(r, bb + (uint32_t)(p * 16 * ASTRIDE * 2));
                    bfr[sb][2 * p][0] = r[0]; bfr[sb][2 * p][1] = r[1];
                    bfr[sb][2 * p + 1][0] = r[2]; bfr[sb][2 * p + 1][1] = r[3];
                }
            }
            uint32_t afr[2][4][4];
#pragma unroll
            for (int sa = 0; sa < 2; sa++) {
                uint32_t ab = base + sa * TILE_B + a_lane_off + koff;
#pragma unroll
                for (int mt = 0; mt < 4; mt++)
                    ldsm_x4(afr[sa][mt], ab + (uint32_t)(mt * 16 * ASTRIDE * 2));
            }
#pragma unroll
            for (int mt = 0; mt < 4; mt++)
#pragma unroll
                for (int nt2 = 0; nt2 < 4; nt2++)
                    mma_f16(acc[mt][nt2], afr[0][mt], bfr[0][nt2]);
#pragma unroll
            for (int mt = 0; mt < 4; mt++)
#pragma unroll
                for (int nt2 = 0; nt2 < 4; nt2++)
                    mma_f16(acc[mt][nt2], afr[0][mt], bfr[1][nt2]);
#pragma unroll
            for (int mt = 0; mt < 4; mt++)
#pragma unroll
                for (int nt2 = 0; nt2 < 4; nt2++)
                    mma_f16(acc[mt][nt2], afr[1][mt], bfr[0][nt2]);
        }
    };

    issue(0);
    CP_WAIT0();
    __syncthreads();

    for (int cc = 0; cc < NCHUNK; cc++) {
        bool more = (cc + 1 < NCHUNK);
        if (more) issue(cc + 1);
        compute(cc & 1);
        if (more) { CP_WAIT0(); __syncthreads(); }
    }

#pragma unroll
    for (int mt = 0; mt < 4; mt++) {
#pragma unroll
        for (int nt2 = 0; nt2 < 4; nt2++) {
            int row = bm + warp_m * 64 + mt * 16 + g;
            int col = bn + warp_n * 32 + nt2 * 8 + tig * 2;
            float2 v0, v1;
            v0.x = gelu_exact(acc[mt][nt2][0] + bias[col]);
            v0.y = gelu_exact(acc[mt][nt2][1] + bias[col + 1]);
            v1.x = gelu_exact(acc[mt][nt2][2] + bias[col]);
            v1.y = gelu_exact(acc[mt][nt2][3] + bias[col + 1]);
            *(float2*)(C + (size_t)row * DIM + col) = v0;
            *(float2*)(C + (size_t)(row + 8) * DIM + col) = v1;
        }
    }
}

// ---------------- fused GEMM1+GEMM3 (M=128, R13 shape) ----------------------
__global__ __launch_bounds__(256, 2)
void fused_gemm_kernel(const __half* __restrict__ Ah, const __half* __restrict__ Al,
                       const __half* __restrict__ Bh, const __half* __restrict__ Bl,
                       const __half* __restrict__ W1h, const __half* __restrict__ W1l,
                       const float* __restrict__ bias,
                       const float* __restrict__ gcol,
                       const float* __restrict__ qa2gate,
                       __half* __restrict__ Yh, __half* __restrict__ Yl,
                       const float* __restrict__ u, const float* __restrict__ wvec,
                       const float* __restrict__ w2, const float* __restrict__ b2,
                       float* __restrict__ logits) {
    extern __shared__ char smem[];
    const unsigned full = 0xffffffffu;
    int tid = threadIdx.x;
    int wid = tid >> 5, lane = tid & 31;
    int warp_m = wid >> 2, warp_n = wid & 3;
    int g = lane >> 2, tig = lane & 3;
    int bm = blockIdx.x * 128;

    uint32_t sbase = (uint32_t)__cvta_generic_to_shared(smem);
    int lrow = lane & 15;
    int lhk  = ((lane >> 4) & 1) * 8;
    uint32_t a_lane_off = (uint32_t)(((warp_m * 64 + lrow) * ASTRIDE + lhk) * 2);
    int bn_off = (lane & 7) + ((lane >> 4) & 1) * 8;
    int bk_off = ((lane >> 3) & 1) * 8;
    uint32_t b_lane_off = (uint32_t)(((warp_n * 32 + bn_off) * ASTRIDE + bk_off) * 2);

    int arow = tid >> 1, ahalf = tid & 1;
    uint32_t stg_lane = (uint32_t)((arow * ASTRIDE + ahalf * 16) * 2);
    size_t a_src_off = (size_t)(bm + arow) * DIM + ahalf * 16;

    float acc[4][4][4];
#pragma unroll
    for (int i = 0; i < 4; i++)
#pragma unroll
        for (int j = 0; j < 4; j++)
#pragma unroll
            for (int r = 0; r < 4; r++) acc[i][j][r] = 0.f;

    float rs[4][2], rss[4][2], rdt[4][2];
#pragma unroll
    for (int i = 0; i < 4; i++) {
        rs[i][0] = rs[i][1] = 0.f;
        rss[i][0] = rss[i][1] = 0.f;
        rdt[i][0] = rdt[i][1] = 0.f;
    }

    auto cp_pair = [&](const __half* Ph, const __half* Pl, size_t off,
                       int cc, int slot) {
        uint32_t dst = sbase + (uint32_t)(cc & 1) * STAGE_B
                     + (uint32_t)slot * (2 * TILE_B) + stg_lane;
        CP16(dst, Ph + off); CP16(dst + 16, Ph + off + 8);
        CP16(dst + TILE_B, Pl + off); CP16(dst + TILE_B + 16, Pl + off + 8);
    };
    auto compute = [&](int st) {
        uint32_t base = sbase + (uint32_t)st * STAGE_B;
#pragma unroll
        for (int ks = 0; ks < 2; ks++) {
            uint32_t koff = (uint32_t)(ks * 16 * 2);
            uint32_t bfr[2][4][2];
#pragma unroll
            for (int sb = 0; sb < 2; sb++) {
                uint32_t bb = base + (2 + sb) * TILE_B + b_lane_off + koff;
#pragma unroll
                for (int p = 0; p < 2; p++) {
                    uint32_t r[4];
                    ldsm_x4(r, bb + (uint32_t)(p * 16 * ASTRIDE * 2));
                    bfr[sb][2 * p][0] = r[0]; bfr[sb][2 * p][1] = r[1];
                    bfr[sb][2 * p + 1][0] = r[2]; bfr[sb][2 * p + 1][1] = r[3];
                }
            }
            uint32_t afr[2][4][4];
#pragma unroll
            for (int sa = 0; sa < 2; sa++) {
                uint32_t ab = base + sa * TILE_B + a_lane_off + koff;
#pragma unroll
                for (int mt = 0; mt < 4; mt++)
                    ldsm_x4(afr[sa][mt], ab + (uint32_t)(mt * 16 * ASTRIDE * 2));
            }
#pragma unroll
            for (int mt = 0; mt < 4; mt++)
#pragma unroll
                for (int nt2 = 0; nt2 < 4; nt2++)
                    mma_f16(acc[mt][nt2], afr[0][mt], bfr[0][nt2]);
#pragma unroll
            for (int mt = 0; mt < 4; mt++)
#pragma unroll
                for (int nt2 = 0; nt2 < 4; nt2++)
                    mma_f16(acc[mt][nt2], afr[0][mt], bfr[1][nt2]);
#pragma unroll
            for (int mt = 0; mt < 4; mt++)
#pragma unroll
                for (int nt2 = 0; nt2 < 4; nt2++)
                    mma_f16(acc[mt][nt2], afr[1][mt], bfr[0][nt2]);
        }
    };

    // ================== PHASE 1: v2 / y / gate stats ==================
    {
        const int NCH = NT1 * NCHUNK;
        auto issue = [&](int cc) {
            int k0 = (cc % NCHUNK) * BK;
            int nt = cc / NCHUNK;
            cp_pair(Ah, Al, a_src_off + k0, cc, 0);
            cp_pair(Bh, Bl, (size_t)(nt * 128 + arow) * DIM + k0 + ahalf * 16, cc, 1);
            CP_COMMIT();
        };
        issue(0); CP_WAIT0(); __syncthreads();
        for (int cc = 0; cc < NCH; cc++) {
            bool more = (cc + 1 < NCH);
            if (more) issue(cc + 1);
            compute(cc & 1);
            if (((cc + 1) % NCHUNK) == 0) {
                int bn = (cc / NCHUNK) * 128;
#pragma unroll
                for (int mt = 0; mt < 4; mt++) {
#pragma unroll
                    for (int nt2 = 0; nt2 < 4; nt2++) {
                        int row = bm + warp_m * 64 + mt * 16 + g;
                        int col = bn + warp_n * 32 + nt2 * 8 + tig * 2;
                        float2 v0, v1;
                        v0.x = gelu_exact(acc[mt][nt2][0] + bias[col]);
                        v0.y = gelu_exact(acc[mt][nt2][1] + bias[col + 1]);
                        v1.x = gelu_exact(acc[mt][nt2][2] + bias[col]);
                        v1.y = gelu_exact(acc[mt][nt2][3] + bias[col + 1]);
                        float2 g2 = *(const float2*)(gcol + col);
                        float y00 = v0.x * g2.x, y01 = v0.y * g2.y;
                        float y10 = v1.x * g2.x, y11 = v1.y * g2.y;
                        __half2 h0 = __floats2half2_rn(y00, y01);
                        __half2 h1 = __floats2half2_rn(y10, y11);
                        __half2 l0 = __floats2half2_rn(y00 - __low2float(h0),
                                                       y01 - __high2float(h0));
                        __half2 l1 = __floats2half2_rn(y10 - __low2float(h1),
                                                       y11 - __high2float(h1));
                        size_t o0 = (size_t)row * DIM + col;
                        size_t o1 = (size_t)(row + 8) * DIM + col;
                        *(uint32_t*)(Yh + o0) = *(uint32_t*)&h0;
                        *(uint32_t*)(Yh + o1) = *(uint32_t*)&h1;
                        *(uint32_t*)(Yl + o0) = *(uint32_t*)&l0;
                        *(uint32_t*)(Yl + o1) = *(uint32_t*)&l1;
                        int b0 = row >> 5;
                        float2 q = *(const float2*)(qa2gate + (size_t)b0 * DIM + col);
                        rs[mt][0]  += v0.x + v0.y;
                        rss[mt][0] += v0.x * v0.x + v0.y * v0.y;
                        rdt[mt][0] += v0.x * q.x + v0.y * q.y;
                        rs[mt][1]  += v1.x + v1.y;
                        rss[mt][1] += v1.x * v1.x + v1.y * v1.y;
                        rdt[mt][1] += v1.x * q.x + v1.y * q.y;
                        acc[mt][nt2][0] = 0.f; acc[mt][nt2][1] = 0.f;
                        acc[mt][nt2][2] = 0.f; acc[mt][nt2][3] = 0.f;
                    }
                }
            }
            if (more) { CP_WAIT0(); __syncthreads(); }
        }
    }

    // ---- gate/LN-fold stats -> smem alpha/m2 ----
    float* sal = (float*)(smem + SAL_OFF);
    float* sm2 = sal + 128;
    {
#pragma unroll
        for (int off = 1; off <= 2; off <<= 1) {
#pragma unroll
            for (int mt = 0; mt < 4; mt++) {
#pragma unroll
                for (int h = 0; h < 2; h++) {
                    rs[mt][h]  += __shfl_xor_sync(full, rs[mt][h],  off);
                    rss[mt][h] += __shfl_xor_sync(full, rss[mt][h], off);
                    rdt[mt][h] += __shfl_xor_sync(full, rdt[mt][h], off);
                }
            }
        }
        float* sred = (float*)(smem + SRED_OFF);
        __syncthreads();   // also orders phase-1 Y stores before phase-2 reads
        if (tig == 0) {
#pragma unroll
            for (int mt = 0; mt < 4; mt++) {
#pragma unroll
                for (int h = 0; h < 2; h++) {
                    int r = warp_m * 64 + mt * 16 + g + h * 8;
                    sred[0 * 512 + warp_n * 128 + r] = rs[mt][h];
                    sred[1 * 512 + warp_n * 128 + r] = rss[mt][h];
                    sred[2 * 512 + warp_n * 128 + r] = rdt[mt][h];
                }
            }
        }
        __syncthreads();
        if (tid < 128) {
            float s = 0.f, ss2 = 0.f, dt = 0.f;
#pragma unroll
            for (int w = 0; w < 4; w++) {
                s   += sred[0 * 512 + w * 128 + tid];
                ss2 += sred[1 * 512 + w * 128 + tid];
                dt  += sred[2 * 512 + w * 128 + tid];
            }
            float m = s / DIM;
            float var = fmaxf(ss2 / DIM - m * m, 0.f);
            float gate = tanhf(dt);
            sm2[tid] = m;
            sal[tid] = gate * rsqrtf(gate * gate * var + LN_EPS);
        }
        __syncthreads();
    }

    // per-row constants for phase 2
    float alp[4][2], mm[4][2];
#pragma unroll
    for (int mt = 0; mt < 4; mt++) {
        int r0 = warp_m * 64 + mt * 16 + g;
        alp[mt][0] = sal[r0];     mm[mt][0] = sm2[r0];
        alp[mt][1] = sal[r0 + 8]; mm[mt][1] = sm2[r0 + 8];
    }

    // ================== PHASE 2: logits ==================
    float dotacc = 0.f;
    {
        const int NCH = NT2 * NCHUNK;
        auto issue = [&](int cc) {
            int k0 = (cc % NCHUNK) * BK;
            int nt = cc / NCHUNK;
            cp_pair(Yh, Yl, a_src_off + k0, cc, 0);
            cp_pair(W1h, W1l, (size_t)(nt * 128 + arow) * DIM + k0 + ahalf * 16, cc, 1);
            CP_COMMIT();
        };
        issue(0); CP_WAIT0(); __syncthreads();
        for (int cc = 0; cc < NCH; cc++) {
            bool more = (cc + 1 < NCH);
            if (more) issue(cc + 1);
            compute(cc & 1);
            if (((cc + 1) % NCHUNK) == 0) {
                int bn = (cc / NCHUNK) * 128;
                float part[4][2];
#pragma unroll
                for (int mt = 0; mt < 4; mt++) { part[mt][0] = 0.f; part[mt][1] = 0.f; }
#pragma unroll
                for (int mt = 0; mt < 4; mt++) {
#pragma unroll
                    for (int nt2 = 0; nt2 < 4; nt2++) {
                        int n0 = bn + warp_n * 32 + nt2 * 8 + tig * 2;
                        float u0 = u[n0], u1 = u[n0 + 1];
                        float wv0 = wvec[n0], wv1 = wvec[n0 + 1];
                        float w20 = w2[n0], w21 = w2[n0 + 1];
                        float h00 = alp[mt][0] * (acc[mt][nt2][0] - mm[mt][0] * u0) + wv0;
                        float h01 = alp[mt][0] * (acc[mt][nt2][1] - mm[mt][0] * u1) + wv1;
                        float h10 = alp[mt][1] * (acc[mt][nt2][2] - mm[mt][1] * u0) + wv0;
                        float h11 = alp[mt][1] * (acc[mt][nt2][3] - mm[mt][1] * u1) + wv1;
                        part[mt][0] += gelu_exact(h00) * w20 + gelu_exact(h01) * w21;
                        part[mt][1] += gelu_exact(h10) * w20 + gelu_exact(h11) * w21;
                        acc[mt][nt2][0] = 0.f; acc[mt][nt2][1] = 0.f;
                        acc[mt][nt2][2] = 0.f; acc[mt][nt2][3] = 0.f;
                    }
                }
#pragma unroll
                for (int off = 1; off <= 2; off <<= 1) {
#pragma unroll
                    for (int mt = 0; mt < 4; mt++) {
                        part[mt][0] += __shfl_xor_sync(full, part[mt][0], off);
                        part[mt][1] += __shfl_xor_sync(full, part[mt][1], off);
                    }
                }
                float* sr = (float*)(smem + SRED_OFF);
                if (tig == 0) {
#pragma unroll
                    for (int mt = 0; mt < 4; mt++) {
                        int r = warp_m * 64 + mt * 16 + g;
                        sr[warp_n * 128 + r] = part[mt][0];
                        sr[warp_n * 128 + r + 8] = part[mt][1];
                    }
                }
                __syncthreads();
                if (tid < 128)
                    dotacc += ((sr[tid] + sr[128 + tid]) + (sr[256 + tid] + sr[384 + tid]));
                __syncthreads();
            }
            if (more) { CP_WAIT0(); __syncthreads(); }
        }
    }

    if (tid < 128)
        logits[bm + tid] = dotacc + b2[0];
}

// ---------------- finalize: shared gaussian kern, warp-parallel search ------
#define OFF_GS     0
#define OFF_MAXIDX (BS * LEN)
#define OFF_START  (BS * LEN + BS * 2)
#define OFF_END    (BS * LEN + BS * 3)
#define OFF_MASK   (BS * LEN + BS * 4)
#define OFF_ORIKEY (BS * LEN * 2 + BS * 4)

__global__ void finalize_kernel(const float* __restrict__ sigma_ptr,
                                float* __restrict__ out) {
    const unsigned full = 0xffffffffu;
    int tid = threadIdx.x;
    int warp = tid >> 5, lane = tid & 31;

    __shared__ double kraw[5];
    __shared__ double kern_s[5];
    if (tid < 5) {
        double sigma = (double)(*sigma_ptr);
        double x = (double)(tid - 2) / sigma;
        kraw[tid] = exp(-0.5 * x * x);
    }
    __syncthreads();
    if (tid < 5) {
        double ks = kraw[0] + kraw[1] + kraw[2] + kraw[3] + kraw[4];
        kern_s[tid] = kraw[tid] / ks;
    }
    __syncthreads();
    double kern[5];
#pragma unroll
    for (int j = 0; j < 5; j++) kern[j] = kern_s[j];

    int b = blockIdx.x * 8 + warp;
    float logit_f = g_logits[b * LEN + lane];
    double logit = (double)logit_f;

    double m = logit;
    for (int o = 16; o; o >>= 1) m = fmax(m, __shfl_xor_sync(full, m, o));
    double e = exp(logit - m);
    double s = e;
    for (int o = 16; o; o >>= 1) s += __shfl_xor_sync(full, s, o);
    double kp = e / s;

    double sm = 0.0;
#pragma unroll
    for (int j = 0; j < 5; j++) {
        int src = lane + j - 2;
        double v = __shfl_sync(full, kp, src & 31);
        if (src >= 0 && src < LEN) sm += kern[j] * v;
    }

    double mg = sm;
    for (int o = 16; o; o >>= 1) mg = fmax(mg, __shfl_xor_sync(full, mg, o));
    double eg = exp(sm - mg);
    double sg = eg;
    for (int o = 16; o; o >>= 1) sg += __shfl_xor_sync(full, sg, o);
    double gs = eg / sg;

    double bv = gs; int bi = lane;
    for (int o = 16; o; o >>= 1) {
        double ov = __shfl_xor_sync(full, bv, o);
        int    oi = __shfl_xor_sync(full, bi, o);
        if (ov > bv || (ov == bv && oi < bi)) { bv = ov; bi = oi; }
    }
    int amax = bi;

    double cs = gs;
#pragma unroll
    for (int off = 1; off < 32; off <<= 1) {
        double t = __shfl_up_sync(full, cs, off);
        if (lane >= off) cs += t;
    }

    double bestv = -INFINITY;
    int bestc = 1 << 20;
#pragma unroll
    for (int r = 0; r < 3; r++) {
        int c = lane + r * 32;
        int w, st;
        if (c < 32)      { w = 1; st = c; }
        else if (c < 62) { w = 3; st = c - 32; }
        else             { w = 5; st = c - 62; }
        bool valid = (c < 90);
        double hi = __shfl_sync(full, cs, (st + w - 1) & 31);
        double lo = __shfl_sync(full, cs, (st - 1) & 31);
        double sum = hi - ((st > 0) ? lo : 0.0);
        bool contains = (amax >= st) && (amax < st + w);
        double val = (valid && contains) ? sum : -INFINITY;
        if (val > bestv || (val == bestv && c < bestc)) { bestv = val; bestc = c; }
    }
    for (int off = 16; off; off >>= 1) {
        double ov = __shfl_xor_sync(full, bestv, off);
        int    oc = __shfl_xor_sync(full, bestc, off);
        if (ov > bestv || (ov == bestv && oc < bestc)) { bestv = ov; bestc = oc; }
    }
    int s0, e0;
    {
        int c = bestc, w, st;
        if (c < 32)      { w = 1; st = c; }
        else if (c < 62) { w = 3; st = c - 32; }
        else             { w = 5; st = c - 62; }
        s0 = st; e0 = st + w;
    }

    out[OFF_GS + b * LEN + lane] = (float)gs;
    if (lane == 0) {
        out[OFF_MAXIDX + b * 2 + 0] = (float)s0;
        out[OFF_MAXIDX + b * 2 + 1] = (float)e0;
        out[OFF_START + b] = (float)s0 / 31.0f;
        out[OFF_END + b]   = (float)e0 / 31.0f;
    }
    out[OFF_MASK + b * LEN + lane] = (lane >= s0 && lane <= e0) ? 1.f : 0.f;
    out[OFF_ORIKEY + b * LEN + lane] = logit_f;
}

// ---------------- launch ----------------------------------------------------
extern "C" void kernel_launch(void* const* d_in, const int* in_sizes, int n_in,
                              void* d_out, int out_size) {
    const float* v       = (const float*)d_in[0];
    const float* qa      = (const float*)d_in[1];
    const float* vp_g    = (const float*)d_in[2];
    const float* vp_b    = (const float*)d_in[3];
    const float* vp_W    = (const float*)d_in[4];
    const float* vp_bias = (const float*)d_in[5];
    const float* qp_g    = (const float*)d_in[6];
    const float* qp_b    = (const float*)d_in[7];
    const float* qp_W    = (const float*)d_in[8];
    const float* qp_bias = (const float*)d_in[9];
    const float* gr_g    = (const float*)d_in[10];
    const float* gr_b    = (const float*)d_in[11];
    const float* gr_W1   = (const float*)d_in[12];
    const float* gr_b1   = (const float*)d_in[13];
    const float* gr_W2   = (const float*)d_in[14];
    const float* gr_b2   = (const float*)d_in[15];
    const float* sigma   = (const float*)d_in[16];
    float* out = (float*)d_out;

    void *p_qa2, *p_lg, *p_u, *p_w;
    void *p_vs, *p_qs, *p_y, *p_vpw, *p_qpw, *p_w1;
    cudaGetSymbolAddress(&p_qa2, g_qa2);
    cudaGetSymbolAddress(&p_lg,  g_logits);
    cudaGetSymbolAddress(&p_u,   g_u);
    cudaGetSymbolAddress(&p_w,   g_w);
    cudaGetSymbolAddress(&p_vs,  g_vs);
    cudaGetSymbolAddress(&p_qs,  g_qs);
    cudaGetSymbolAddress(&p_y,   g_y);
    cudaGetSymbolAddress(&p_vpw, g_vpW_s);
    cudaGetSymbolAddress(&p_qpw, g_qpW_s);
    cudaGetSymbolAddress(&p_w1,  g_grW1_s);

    __half* vs  = (__half*)p_vs;
    __half* qs  = (__half*)p_qs;
    __half* yy  = (__half*)p_y;
    __half* vpw = (__half*)p_vpw;
    __half* qpw = (__half*)p_qpw;
    __half* w1s = (__half*)p_w1;
    const size_t VN = (size_t)ROWS * DIM;
    const size_t QN = (size_t)BS * DIM;

    cudaFuncSetAttribute((const void*)stage2_kernel,
                         cudaFuncAttributeMaxDynamicSharedMemorySize, SMEM_DYN);
    cudaFuncSetAttribute((const void*)fused_gemm_kernel,
                         cudaFuncAttributeMaxDynamicSharedMemorySize, SMEM_DYN);

    // [1] transposes + LN-split(qa) + u/w (all independent, one launch)
    prep_stage1<<<S1_BLOCKS, 256>>>(
        vp_W, qp_W, gr_W1, vpw, qpw, w1s,
        qa, qp_g, qp_b, qs, qs + QN,
        gr_g, gr_b, gr_b1, (float*)p_u, (float*)p_w);

    // [2] qa2 GEMM tiles + LN-split(v) co-scheduled (tensor + memory overlap)
    stage2_kernel<<<S2_BLOCKS, 256, SMEM_DYN>>>(
        qs, qs + QN, qpw, qpw + (size_t)DIM * DIM, qp_bias, (float*)p_qa2,
        v, vp_g, vp_b, vs, vs + VN);

    // [3] fused GEMM1+GEMM3 (M=128, proven R13 shape)
    fused_gemm_kernel<<<ROWS / 128, 256, SMEM_DYN>>>(
        vs, vs + VN, vpw, vpw + (size_t)DIM * DIM,
        w1s, w1s + (size_t)HID * DIM,
        vp_bias, gr_g, (const float*)p_qa2,
        yy, yy + VN,
        (const float*)p_u, (const float*)p_w,
        gr_W2, gr_b2, (float*)p_lg);

    // [4] finalize
    finalize_kernel<<<BS / 8, 256>>>(sigma, out);
}

// round 17
// speedup vs baseline: 1.0581x; 1.0096x over previous
#include <cuda_runtime.h>
#include <cuda_fp16.h>
#include <math.h>
#include <stdint.h>

#define BS   4096
#define LEN  32
#define DIM  768
#define HID  384
#define ROWS (BS * LEN)          // 131072
#define LN_EPS 1e-5f

// ---- mma tiling ----
#define BK 32
#define NCHUNK (DIM / BK)        // 24
#define NT1 (DIM / 128)          // 6
#define NT2 (HID / 128)          // 3
#define ASTRIDE 40               // fp16 elems per smem row (80B, 16B-divisible)
#define TILE_B (128 * ASTRIDE * 2)   // 10240 bytes per split tile
#define STAGE_B (4 * TILE_B)         // A_hi,A_lo,B_hi,B_lo = 40960
#define SRED_OFF (2 * STAGE_B)       // 81920
#define SAL_OFF  (SRED_OFF + 3 * 512 * 4)   // 88064
#define SMEM_DYN (SAL_OFF + 2 * 128 * 4)    // 89088  (x2 CTAs <= 228KB)

// stage-1 combined grid layout
#define TR_BLOCKS   (24 * 24 * 3)            // 1728 transpose tiles
#define QAP_BLOCKS  (BS / 8)                 // 512 qa LN-split blocks
#define UW_BLOCKS   (HID / 8)                // 48 u/w blocks
#define S1_BLOCKS   (TR_BLOCKS + QAP_BLOCKS + UW_BLOCKS)
// stage-2 combined grid layout
#define QA2_BLOCKS  ((BS / 128) * (DIM / 128))   // 192
#define PV_ROWS_PER_BLOCK 64
#define PV_BLOCKS   (ROWS / PV_ROWS_PER_BLOCK)   // 2048
#define S2_BLOCKS   (QA2_BLOCKS + PV_BLOCKS)

// output layout (fp32): gs | max_idx | start_t | end_t | mask | ori_key
#define OFF_GS     0
#define OFF_MAXIDX (BS * LEN)
#define OFF_START  (BS * LEN + BS * 2)
#define OFF_END    (BS * LEN + BS * 3)
#define OFF_MASK   (BS * LEN + BS * 4)
#define OFF_ORIKEY (BS * LEN * 2 + BS * 4)

// ---------------- scratch (device globals; no runtime allocation) ----------
__device__ float g_qa2[BS * DIM];
__device__ float g_u[HID];
__device__ float g_w[HID];
// pre-split operands (hi at 0, lo at +count)
__device__ __align__(16) __half g_vs[2 * (size_t)ROWS * DIM];   // LN(v) split
__device__ __align__(16) __half g_qs[2 * (size_t)BS * DIM];     // LN(qa) split
__device__ __align__(16) __half g_y [2 * (size_t)ROWS * DIM];   // v2*g split
// transposed+split weights, [split][n][k]
__device__ __align__(16) __half g_vpW_s[2 * DIM * DIM];
__device__ __align__(16) __half g_qpW_s[2 * DIM * DIM];
__device__ __align__(16) __half g_grW1_s[2 * HID * DIM];

__device__ __forceinline__ float gelu_exact(float x) {
    return 0.5f * x * (1.0f + erff(x * 0.70710678118654752440f));
}
__device__ __forceinline__ void mma_f16(float* d, const uint32_t* a, const uint32_t* b) {
    asm volatile(
        "mma.sync.aligned.m16n8k16.row.col.f32.f16.f16.f32 "
        "{%0,%1,%2,%3}, {%4,%5,%6,%7}, {%8,%9}, {%0,%1,%2,%3};"
        : "+f"(d[0]), "+f"(d[1]), "+f"(d[2]), "+f"(d[3])
        : "r"(a[0]), "r"(a[1]), "r"(a[2]), "r"(a[3]), "r"(b[0]), "r"(b[1]));
}
__device__ __forceinline__ void ldsm_x4(uint32_t* r, uint32_t addr) {
    asm volatile("ldmatrix.sync.aligned.m8n8.x4.shared.b16 {%0,%1,%2,%3}, [%4];"
                 : "=r"(r[0]), "=r"(r[1]), "=r"(r[2]), "=r"(r[3]) : "r"(addr));
}
// L2-direct (bypass L1): GEMM staging never re-reads through L1
#define CP16(dst, src) \
    asm volatile("cp.async.cg.shared.global [%0], [%1], 16;" :: "r"(dst), "l"(src))
#define CP_COMMIT() asm volatile("cp.async.commit_group;")
#define CP_WAIT0()  asm volatile("cp.async.wait_group 0;")

// ---------------- device helper: LN fold + fp16 split of one row ------------
__device__ __forceinline__ void ln_split_row(const float* __restrict__ X,
                                             const float* __restrict__ lng,
                                             const float* __restrict__ lnb,
                                             __half* __restrict__ Sh,
                                             __half* __restrict__ Sl,
                                             int row, int lane) {
    const float* x = X + (size_t)row * DIM;
    float4 xv[6];
    float s = 0.f, ss = 0.f;
#pragma unroll
    for (int i = 0; i < 6; i++) {
        xv[i] = *(const float4*)(x + i * 128 + lane * 4);
        s += xv[i].x + xv[i].y + xv[i].z + xv[i].w;
        ss = fmaf(xv[i].x, xv[i].x, ss);
        ss = fmaf(xv[i].y, xv[i].y, ss);
        ss = fmaf(xv[i].z, xv[i].z, ss);
        ss = fmaf(xv[i].w, xv[i].w, ss);
    }
    for (int o = 16; o; o >>= 1) {
        s  += __shfl_xor_sync(0xffffffffu, s,  o);
        ss += __shfl_xor_sync(0xffffffffu, ss, o);
    }
    float m = s / DIM;
    float rstd = rsqrtf(fmaxf(ss / DIM - m * m, 0.f) + LN_EPS);
#pragma unroll
    for (int i = 0; i < 6; i++) {
        int k = i * 128 + lane * 4;
        float4 g4 = *(const float4*)(lng + k);
        float4 b4 = *(const float4*)(lnb + k);
        float x0 = fmaf(xv[i].x - m, rstd * g4.x, b4.x);
        float x1 = fmaf(xv[i].y - m, rstd * g4.y, b4.y);
        float x2 = fmaf(xv[i].z - m, rstd * g4.z, b4.z);
        float x3 = fmaf(xv[i].w - m, rstd * g4.w, b4.w);
        __half2 h01 = __floats2half2_rn(x0, x1);
        __half2 h23 = __floats2half2_rn(x2, x3);
        float r0 = x0 - __low2float(h01), r1 = x1 - __high2float(h01);
        float r2 = x2 - __low2float(h23), r3 = x3 - __high2float(h23);
        __half2 l01 = __floats2half2_rn(r0, r1);
        __half2 l23 = __floats2half2_rn(r2, r3);
        size_t off = (size_t)row * DIM + k;
        *(uint2*)(Sh + off) = make_uint2(*(uint32_t*)&h01, *(uint32_t*)&h23);
        *(uint2*)(Sl + off) = make_uint2(*(uint32_t*)&l01, *(uint32_t*)&l23);
    }
}

// ---------------- two rows concurrently (doubled MLP; per-row math identical)
__device__ __forceinline__ void ln_split_row2(const float* __restrict__ X,
                                              const float* __restrict__ lng,
                                              const float* __restrict__ lnb,
                                              __half* __restrict__ Sh,
                                              __half* __restrict__ Sl,
                                              int rowA, int rowB, int lane) {
    const float* xa = X + (size_t)rowA * DIM;
    const float* xb = X + (size_t)rowB * DIM;
    float4 va[6], vb[6];
#pragma unroll
    for (int i = 0; i < 6; i++) {
        va[i] = *(const float4*)(xa + i * 128 + lane * 4);
        vb[i] = *(const float4*)(xb + i * 128 + lane * 4);
    }
    float sa = 0.f, ssa = 0.f, sb = 0.f, ssb = 0.f;
#pragma unroll
    for (int i = 0; i < 6; i++) {
        sa += va[i].x + va[i].y + va[i].z + va[i].w;
        ssa = fmaf(va[i].x, va[i].x, ssa);
        ssa = fmaf(va[i].y, va[i].y, ssa);
        ssa = fmaf(va[i].z, va[i].z, ssa);
        ssa = fmaf(va[i].w, va[i].w, ssa);
        sb += vb[i].x + vb[i].y + vb[i].z + vb[i].w;
        ssb = fmaf(vb[i].x, vb[i].x, ssb);
        ssb = fmaf(vb[i].y, vb[i].y, ssb);
        ssb = fmaf(vb[i].z, vb[i].z, ssb);
        ssb = fmaf(vb[i].w, vb[i].w, ssb);
    }
    for (int o = 16; o; o >>= 1) {
        sa  += __shfl_xor_sync(0xffffffffu, sa,  o);
        ssa += __shfl_xor_sync(0xffffffffu, ssa, o);
        sb  += __shfl_xor_sync(0xffffffffu, sb,  o);
        ssb += __shfl_xor_sync(0xffffffffu, ssb, o);
    }
    float ma = sa / DIM;
    float ra = rsqrtf(fmaxf(ssa / DIM - ma * ma, 0.f) + LN_EPS);
    float mb = sb / DIM;
    float rb = rsqrtf(fmaxf(ssb / DIM - mb * mb, 0.f) + LN_EPS);
#pragma unroll
    for (int i = 0; i < 6; i++) {
        int k = i * 128 + lane * 4;
        float4 g4 = *(const float4*)(lng + k);
        float4 b4 = *(const float4*)(lnb + k);
        {
            float x0 = fmaf(va[i].x - ma, ra * g4.x, b4.x);
            float x1 = fmaf(va[i].y - ma, ra * g4.y, b4.y);
            float x2 = fmaf(va[i].z - ma, ra * g4.z, b4.z);
            float x3 = fmaf(va[i].w - ma, ra * g4.w, b4.w);
            __half2 h01 = __floats2half2_rn(x0, x1);
            __half2 h23 = __floats2half2_rn(x2, x3);
            float r0 = x0 - __low2float(h01), r1 = x1 - __high2float(h01);
            float r2 = x2 - __low2float(h23), r3 = x3 - __high2float(h23);
            __half2 l01 = __floats2half2_rn(r0, r1);
            __half2 l23 = __floats2half2_rn(r2, r3);
            size_t off = (size_t)rowA * DIM + k;
            *(uint2*)(Sh + off) = make_uint2(*(uint32_t*)&h01, *(uint32_t*)&h23);
            *(uint2*)(Sl + off) = make_uint2(*(uint32_t*)&l01, *(uint32_t*)&l23);
        }
        {
            float x0 = fmaf(vb[i].x - mb, rb * g4.x, b4.x);
            float x1 = fmaf(vb[i].y - mb, rb * g4.y, b4.y);
            float x2 = fmaf(vb[i].z - mb, rb * g4.z, b4.z);
            float x3 = fmaf(vb[i].w - mb, rb * g4.w, b4.w);
            __half2 h01 = __floats2half2_rn(x0, x1);
            __half2 h23 = __floats2half2_rn(x2, x3);
            float r0 = x0 - __low2float(h01), r1 = x1 - __high2float(h01);
            float r2 = x2 - __low2float(h23), r3 = x3 - __high2float(h23);
            __half2 l01 = __floats2half2_rn(r0, r1);
            __half2 l23 = __floats2half2_rn(r2, r3);
            size_t off = (size_t)rowB * DIM + k;
            *(uint2*)(Sh + off) = make_uint2(*(uint32_t*)&h01, *(uint32_t*)&h23);
            *(uint2*)(Sl + off) = make_uint2(*(uint32_t*)&l01, *(uint32_t*)&l23);
        }
    }
}

// ---------------- stage 1: transposes + LN-split(qa) + u/w ------------------
__global__ void prep_stage1(const float* __restrict__ vpW,
                            const float* __restrict__ qpW,
                            const float* __restrict__ W1,
                            __half* __restrict__ vout,
                            __half* __restrict__ qout,
                            __half* __restrict__ w1out,
                            const float* __restrict__ qa,
                            const float* __restrict__ qp_g,
                            const float* __restrict__ qp_b,
                            __half* __restrict__ qsh, __half* __restrict__ qsl,
                            const float* __restrict__ gr_g,
                            const float* __restrict__ gr_b,
                            const float* __restrict__ gr_b1,
                            float* __restrict__ u, float* __restrict__ w) {
    int b = blockIdx.x;
    int tid = threadIdx.x;
    if (b < TR_BLOCKS) {
        int z = b / 576, rem = b % 576;
        const float* W; __half* Ws; int N;
        if (z == 0)      { W = vpW; Ws = vout;  N = DIM; }
        else if (z == 1) { W = qpW; Ws = qout;  N = DIM; }
        else             { W = W1;  Ws = w1out; N = HID; }
        int n0 = (rem % 24) * 32, k0 = (rem / 24) * 32;
        if (n0 >= N) return;
        __shared__ float t[32][33];
        int tx = tid & 31, ty = tid >> 5;   // 32 x 8
#pragma unroll
        for (int i = 0; i < 4; i++)
            t[ty + i * 8][tx] = W[(size_t)(k0 + ty + i * 8) * N + n0 + tx];
        __syncthreads();
        size_t ss = (size_t)N * DIM;
#pragma unroll
        for (int i = 0; i < 4; i++) {
            int n = n0 + ty + i * 8;
            float x = t[tx][ty + i * 8];
            __half hb = __float2half_rn(x);
            float r = x - __half2float(hb);
            __half lb = __float2half_rn(r);
            size_t o = (size_t)n * DIM + k0 + tx;
            Ws[o] = hb; Ws[ss + o] = lb;
        }
    } else if (b < TR_BLOCKS + QAP_BLOCKS) {
        int row = (b - TR_BLOCKS) * 8 + (tid >> 5);
        ln_split_row(qa, qp_g, qp_b, qsh, qsl, row, tid & 31);
    } else {
        int n = (b - TR_BLOCKS - QAP_BLOCKS) * 8 + (tid >> 5);
        if (n >= HID) return;
        int lane = tid & 31;
        float su = 0.f, sw = 0.f;
        for (int k = lane; k < DIM; k += 32) {
            float wv = W1[(size_t)k * HID + n];
            su = fmaf(gr_g[k], wv, su);
            sw = fmaf(gr_b[k], wv, sw);
        }
        for (int o = 16; o; o >>= 1) {
            su += __shfl_xor_sync(0xffffffffu, su, o);
            sw += __shfl_xor_sync(0xffffffffu, sw, o);
        }
        if (lane == 0) { u[n] = su; w[n] = sw + gr_b1[n]; }
    }
}

// ---------------- stage 2: qa2 GEMM tiles + LN-split(v), co-scheduled -------
__global__ __launch_bounds__(256, 2)
void stage2_kernel(const __half* __restrict__ Ah, const __half* __restrict__ Al,
                   const __half* __restrict__ Bh, const __half* __restrict__ Bl,
                   const float* __restrict__ bias,
                   float* __restrict__ C,
                   const float* __restrict__ v,
                   const float* __restrict__ vp_g,
                   const float* __restrict__ vp_b,
                   __half* __restrict__ vsh, __half* __restrict__ vsl) {
    extern __shared__ char smem[];
    int tid = threadIdx.x;

    if (blockIdx.x >= QA2_BLOCKS) {
        // ---- prep_v path: LN fold + split of 64 v rows, 2 at a time ----
        int row0 = (blockIdx.x - QA2_BLOCKS) * PV_ROWS_PER_BLOCK + (tid >> 5) * 8;
        int lane = tid & 31;
#pragma unroll
        for (int i = 0; i < 8; i += 2)
            ln_split_row2(v, vp_g, vp_b, vsh, vsl, row0 + i, row0 + i + 1, lane);
        return;
    }

    int wid = tid >> 5, lane = tid & 31;
    int warp_m = wid >> 2, warp_n = wid & 3;
    int g = lane >> 2, tig = lane & 3;
    int bm = (blockIdx.x % (BS / 128)) * 128;
    int bn = (blockIdx.x / (BS / 128)) * 128;

    uint32_t sbase = (uint32_t)__cvta_generic_to_shared(smem);
    int lrow = lane & 15;
    int lhk  = ((lane >> 4) & 1) * 8;
    uint32_t a_lane_off = (uint32_t)(((warp_m * 64 + lrow) * ASTRIDE + lhk) * 2);
    int bn_off = (lane & 7) + ((lane >> 4) & 1) * 8;
    int bk_off = ((lane >> 3) & 1) * 8;
    uint32_t b_lane_off = (uint32_t)(((warp_n * 32 + bn_off) * ASTRIDE + bk_off) * 2);

    int arow = tid >> 1, ahalf = tid & 1;
    uint32_t stg_lane = (uint32_t)((arow * ASTRIDE + ahalf * 16) * 2);
    size_t a_src_off = (size_t)(bm + arow) * DIM + ahalf * 16;
    size_t b_src_off = (size_t)(bn + arow) * DIM + ahalf * 16;

    float acc[4][4][4];
#pragma unroll
    for (int i = 0; i < 4; i++)
#pragma unroll
        for (int j = 0; j < 4; j++)
#pragma unroll
            for (int r = 0; r < 4; r++) acc[i][j][r] = 0.f;

    auto issue = [&](int cc) {
        int k0 = cc * BK;
        uint32_t dst = sbase + (uint32_t)(cc & 1) * STAGE_B + stg_lane;
        const __half* sh = Ah + a_src_off + k0;
        const __half* sl = Al + a_src_off + k0;
        CP16(dst, sh); CP16(dst + 16, sh + 8);
        CP16(dst + TILE_B, sl); CP16(dst + TILE_B + 16, sl + 8);
        const __half* th = Bh + b_src_off + k0;
        const __half* tl = Bl + b_src_off + k0;
        uint32_t dstb = dst + 2 * TILE_B;
        CP16(dstb, th); CP16(dstb + 16, th + 8);
        CP16(dstb + TILE_B, tl); CP16(dstb + TILE_B + 16, tl + 8);
        CP_COMMIT();
    };
    auto compute = [&](int st) {
        uint32_t base = sbase + (uint32_t)st * STAGE_B;
#pragma unroll
        for (int ks = 0; ks < 2; ks++) {
            uint32_t koff = (uint32_t)(ks * 16 * 2);
            uint32_t bfr[2][4][2];
#pragma unroll
            for (int sb = 0; sb < 2; sb++) {
                uint32_t bb = base + (2 + sb) * TILE_B + b_lane_off + koff;
#pragma unroll
                for (int p = 0; p < 2; p++) {
                    uint32_t r[4];
                    ldsm_x4(r, bb + (uint32_t)(p * 16 * ASTRIDE * 2));
                    bfr[sb][2 * p][0] = r[0]; bfr[sb][2 * p][1] = r[1];
                    bfr[sb][2 * p + 1][0] = r[2]; bfr[sb][2 * p + 1][1] = r[3];
                }
            }
            uint32_t afr[2][4][4];
#pragma unroll
            for (int sa = 0; sa < 2; sa++) {
                uint32_t ab = base + sa * TILE_B + a_lane_off + koff;
#pragma unroll
                for (int mt = 0; mt < 4; mt++)
                    ldsm_x4(afr[sa][mt], ab + (uint32_t)(mt * 16 * ASTRIDE * 2));
            }
#pragma unroll
            for (int mt = 0; mt < 4; mt++)
#pragma unroll
                for (int nt2 = 0; nt2 < 4; nt2++)
                    mma_f16(acc[mt][nt2], afr[0][mt], bfr[0][nt2]);
#pragma unroll
            for (int mt = 0; mt < 4; mt++)
#pragma unroll
                for (int nt2 = 0; nt2 < 4; nt2++)
                    mma_f16(acc[mt][nt2], afr[0][mt], bfr[1][nt2]);
#pragma unroll
            for (int mt = 0; mt < 4; mt++)
#pragma unroll
                for (int nt2 = 0; nt2 < 4; nt2++)
                    mma_f16(acc[mt][nt2], afr[1][mt], bfr[0][nt2]);
        }
    };

    issue(0);
    CP_WAIT0();
    __syncthreads();

    for (int cc = 0; cc < NCHUNK; cc++) {
        bool more = (cc + 1 < NCHUNK);
        if (more) issue(cc + 1);
        compute(cc & 1);
        if (more) { CP_WAIT0(); __syncthreads(); }
    }

#pragma unroll
    for (int mt = 0; mt < 4; mt++) {
#pragma unroll
        for (int nt2 = 0; nt2 < 4; nt2++) {
            int row = bm + warp_m * 64 + mt * 16 + g;
            int col = bn + warp_n * 32 + nt2 * 8 + tig * 2;
            float2 v0, v1;
            v0.x = gelu_exact(acc[mt][nt2][0] + bias[col]);
            v0.y = gelu_exact(acc[mt][nt2][1] + bias[col + 1]);
            v1.x = gelu_exact(acc[mt][nt2][2] + bias[col]);
            v1.y = gelu_exact(acc[mt][nt2][3] + bias[col + 1]);
            *(float2*)(C + (size_t)row * DIM + col) = v0;
            *(float2*)(C + (size_t)(row + 8) * DIM + col) = v1;
        }
    }
}

// ---------------- fused GEMM1+GEMM3 + finalize tail -------------------------
__global__ __launch_bounds__(256, 2)
void fused_gemm_kernel(const __half* __restrict__ Ah, const __half* __restrict__ Al,
                       const __half* __restrict__ Bh, const __half* __restrict__ Bl,
                       const __half* __restrict__ W1h, const __half* __restrict__ W1l,
                       const float* __restrict__ bias,
                       const float* __restrict__ gcol,
                       const float* __restrict__ qa2gate,
                       __half* __restrict__ Yh, __half* __restrict__ Yl,
                       const float* __restrict__ u, const float* __restrict__ wvec,
                       const float* __restrict__ w2, const float* __restrict__ b2,
                       const float* __restrict__ sigma_ptr,
                       float* __restrict__ out) {
    extern __shared__ char smem[];
    const unsigned full = 0xffffffffu;
    int tid = threadIdx.x;
    int wid = tid >> 5, lane = tid & 31;
    int warp_m = wid >> 2, warp_n = wid & 3;
    int g = lane >> 2, tig = lane & 3;
    int bm = blockIdx.x * 128;

    uint32_t sbase = (uint32_t)__cvta_generic_to_shared(smem);
    int lrow = lane & 15;
    int lhk  = ((lane >> 4) & 1) * 8;
    uint32_t a_lane_off = (uint32_t)(((warp_m * 64 + lrow) * ASTRIDE + lhk) * 2);
    int bn_off = (lane & 7) + ((lane >> 4) & 1) * 8;
    int bk_off = ((lane >> 3) & 1) * 8;
    uint32_t b_lane_off = (uint32_t)(((warp_n * 32 + bn_off) * ASTRIDE + bk_off) * 2);

    int arow = tid >> 1, ahalf = tid & 1;
    uint32_t stg_lane = (uint32_t)((arow * ASTRIDE + ahalf * 16) * 2);
    size_t a_src_off = (size_t)(bm + arow) * DIM + ahalf * 16;

    float acc[4][4][4];
#pragma unroll
    for (int i = 0; i < 4; i++)
#pragma unroll
        for (int j = 0; j < 4; j++)
#pragma unroll
            for (int r = 0; r < 4; r++) acc[i][j][r] = 0.f;

    float rs[4][2], rss[4][2], rdt[4][2];
#pragma unroll
    for (int i = 0; i < 4; i++) {
        rs[i][0] = rs[i][1] = 0.f;
        rss[i][0] = rss[i][1] = 0.f;
        rdt[i][0] = rdt[i][1] = 0.f;
    }

    auto cp_pair = [&](const __half* Ph, const __half* Pl, size_t off,
                       int cc, int slot) {
        uint32_t dst = sbase + (uint32_t)(cc & 1) * STAGE_B
                     + (uint32_t)slot * (2 * TILE_B) + stg_lane;
        CP16(dst, Ph + off); CP16(dst + 16, Ph + off + 8);
        CP16(dst + TILE_B, Pl + off); CP16(dst + TILE_B + 16, Pl + off + 8);
    };
    auto compute = [&](int st) {
        uint32_t base = sbase + (uint32_t)st * STAGE_B;
#pragma unroll
        for (int ks = 0; ks < 2; ks++) {
            uint32_t koff = (uint32_t)(ks * 16 * 2);
            uint32_t bfr[2][4][2];
#pragma unroll
            for (int sb = 0; sb < 2; sb++) {
                uint32_t bb = base + (2 + sb) * TILE_B + b_lane_off + koff;
#pragma unroll
                for (int p = 0; p < 2; p++) {
                    uint32_t r[4];
                    ldsm_x4(r, bb + (uint32_t)(p * 16 * ASTRIDE * 2));
                    bfr[sb][2 * p][0] = r[0]; bfr[sb][2 * p][1] = r[1];
                    bfr[sb][2 * p + 1][0] = r[2]; bfr[sb][2 * p + 1][1] = r[3];
                }
            }
            uint32_t afr[2][4][4];
#pragma unroll
            for (int sa = 0; sa < 2; sa++) {
                uint32_t ab = base + sa * TILE_B + a_lane_off + koff;
#pragma unroll
                for (int mt = 0; mt < 4; mt++)
                    ldsm_x4(afr[sa][mt], ab + (uint32_t)(mt * 16 * ASTRIDE * 2));
            }
#pragma unroll
            for (int mt = 0; mt < 4; mt++)
#pragma unroll
                for (int nt2 = 0; nt2 < 4; nt2++)
                    mma_f16(acc[mt][nt2], afr[0][mt], bfr[0][nt2]);
#pragma unroll
            for (int mt = 0; mt < 4; mt++)
#pragma unroll
                for (int nt2 = 0; nt2 < 4; nt2++)
                    mma_f16(acc[mt][nt2], afr[0][mt], bfr[1][nt2]);
#pragma unroll
            for (int mt = 0; mt < 4; mt++)
#pragma unroll
                for (int nt2 = 0; nt2 < 4; nt2++)
                    mma_f16(acc[mt][nt2], afr[1][mt], bfr[0][nt2]);
        }
    };

    // ================== PHASE 1: v2 / y / gate stats ==================
    {
        const int NCH = NT1 * NCHUNK;
        auto issue = [&](int cc) {
            int k0 = (cc % NCHUNK) * BK;
            int nt = cc / NCHUNK;
            cp_pair(Ah, Al, a_src_off + k0, cc, 0);
            cp_pair(Bh, Bl, (size_t)(nt * 128 + arow) * DIM + k0 + ahalf * 16, cc, 1);
            CP_COMMIT();
        };
        issue(0); CP_WAIT0(); __syncthreads();
        for (int cc = 0; cc < NCH; cc++) {
            bool more = (cc + 1 < NCH);
            if (more) issue(cc + 1);
            compute(cc & 1);
            if (((cc + 1) % NCHUNK) == 0) {
                int bn = (cc / NCHUNK) * 128;
#pragma unroll
                for (int mt = 0; mt < 4; mt++) {
#pragma unroll
                    for (int nt2 = 0; nt2 < 4; nt2++) {
                        int row = bm + warp_m * 64 + mt * 16 + g;
                        int col = bn + warp_n * 32 + nt2 * 8 + tig * 2;
                        float2 v0, v1;
                        v0.x = gelu_exact(acc[mt][nt2][0] + bias[col]);
                        v0.y = gelu_exact(acc[mt][nt2][1] + bias[col + 1]);
                        v1.x = gelu_exact(acc[mt][nt2][2] + bias[col]);
                        v1.y = gelu_exact(acc[mt][nt2][3] + bias[col + 1]);
                        float2 g2 = *(const float2*)(gcol + col);
                        float y00 = v0.x * g2.x, y01 = v0.y * g2.y;
                        float y10 = v1.x * g2.x, y11 = v1.y * g2.y;
                        __half2 h0 = __floats2half2_rn(y00, y01);
                        __half2 h1 = __floats2half2_rn(y10, y11);
                        __half2 l0 = __floats2half2_rn(y00 - __low2float(h0),
                                                       y01 - __high2float(h0));
                        __half2 l1 = __floats2half2_rn(y10 - __low2float(h1),
                                                       y11 - __high2float(h1));
                        size_t o0 = (size_t)row * DIM + col;
                        size_t o1 = (size_t)(row + 8) * DIM + col;
                        *(uint32_t*)(Yh + o0) = *(uint32_t*)&h0;
                        *(uint32_t*)(Yh + o1) = *(uint32_t*)&h1;
                        *(uint32_t*)(Yl + o0) = *(uint32_t*)&l0;
                        *(uint32_t*)(Yl + o1) = *(uint32_t*)&l1;
                        int b0 = row >> 5;
                        float2 q = *(const float2*)(qa2gate + (size_t)b0 * DIM + col);
                        rs[mt][0]  += v0.x + v0.y;
                        rss[mt][0] += v0.x * v0.x + v0.y * v0.y;
                        rdt[mt][0] += v0.x * q.x + v0.y * q.y;
                        rs[mt][1]  += v1.x + v1.y;
                        rss[mt][1] += v1.x * v1.x + v1.y * v1.y;
                        rdt[mt][1] += v1.x * q.x + v1.y * q.y;
                        acc[mt][nt2][0] = 0.f; acc[mt][nt2][1] = 0.f;
                        acc[mt][nt2][2] = 0.f; acc[mt][nt2][3] = 0.f;
                    }
                }
            }
            if (more) { CP_WAIT0(); __syncthreads(); }
        }
    }

    // ---- gate/LN-fold stats -> smem alpha/m2 ----
    float* sal = (float*)(smem + SAL_OFF);
    float* sm2 = sal + 128;
    {
#pragma unroll
        for (int off = 1; off <= 2; off <<= 1) {
#pragma unroll
            for (int mt = 0; mt < 4; mt++) {
#pragma unroll
                for (int h = 0; h < 2; h++) {
                    rs[mt][h]  += __shfl_xor_sync(full, rs[mt][h],  off);
                    rss[mt][h] += __shfl_xor_sync(full, rss[mt][h], off);
                    rdt[mt][h] += __shfl_xor_sync(full, rdt[mt][h], off);
                }
            }
        }
        float* sred = (float*)(smem + SRED_OFF);
        __syncthreads();   // also orders phase-1 Y stores before phase-2 reads
        if (tig == 0) {
#pragma unroll
            for (int mt = 0; mt < 4; mt++) {
#pragma unroll
                for (int h = 0; h < 2; h++) {
                    int r = warp_m * 64 + mt * 16 + g + h * 8;
                    sred[0 * 512 + warp_n * 128 + r] = rs[mt][h];
                    sred[1 * 512 + warp_n * 128 + r] = rss[mt][h];
                    sred[2 * 512 + warp_n * 128 + r] = rdt[mt][h];
                }
            }
        }
        __syncthreads();
        if (tid < 128) {
            float s = 0.f, ss2 = 0.f, dt = 0.f;
#pragma unroll
            for (int w = 0; w < 4; w++) {
                s   += sred[0 * 512 + w * 128 + tid];
                ss2 += sred[1 * 512 + w * 128 + tid];
                dt  += sred[2 * 512 + w * 128 + tid];
            }
            float m = s / DIM;
            float var = fmaxf(ss2 / DIM - m * m, 0.f);
            float gate = tanhf(dt);
            sm2[tid] = m;
            sal[tid] = gate * rsqrtf(gate * gate * var + LN_EPS);
        }
        __syncthreads();
    }

    // per-row constants for phase 2
    float alp[4][2], mm[4][2];
#pragma unroll
    for (int mt = 0; mt < 4; mt++) {
        int r0 = warp_m * 64 + mt * 16 + g;
        alp[mt][0] = sal[r0];     mm[mt][0] = sm2[r0];
        alp[mt][1] = sal[r0 + 8]; mm[mt][1] = sm2[r0 + 8];
    }

    // ================== PHASE 2: logits ==================
    float dotacc = 0.f;
    {
        const int NCH = NT2 * NCHUNK;
        auto issue = [&](int cc) {
            int k0 = (cc % NCHUNK) * BK;
            int nt = cc / NCHUNK;
            cp_pair(Yh, Yl, a_src_off + k0, cc, 0);
            cp_pair(W1h, W1l, (size_t)(nt * 128 + arow) * DIM + k0 + ahalf * 16, cc, 1);
            CP_COMMIT();
        };
        issue(0); CP_WAIT0(); __syncthreads();
        for (int cc = 0; cc < NCH; cc++) {
            bool more = (cc + 1 < NCH);
            if (more) issue(cc + 1);
            compute(cc & 1);
            if (((cc + 1) % NCHUNK) == 0) {
                int bn = (cc / NCHUNK) * 128;
                float part[4][2];
#pragma unroll
                for (int mt = 0; mt < 4; mt++) { part[mt][0] = 0.f; part[mt][1] = 0.f; }
#pragma unroll
                for (int mt = 0; mt < 4; mt++) {
#pragma unroll
                    for (int nt2 = 0; nt2 < 4; nt2++) {
                        int n0 = bn + warp_n * 32 + nt2 * 8 + tig * 2;
                        float u0 = u[n0], u1 = u[n0 + 1];
                        float wv0 = wvec[n0], wv1 = wvec[n0 + 1];
                        float w20 = w2[n0], w21 = w2[n0 + 1];
                        float h00 = alp[mt][0] * (acc[mt][nt2][0] - mm[mt][0] * u0) + wv0;
                        float h01 = alp[mt][0] * (acc[mt][nt2][1] - mm[mt][0] * u1) + wv1;
                        float h10 = alp[mt][1] * (acc[mt][nt2][2] - mm[mt][1] * u0) + wv0;
                        float h11 = alp[mt][1] * (acc[mt][nt2][3] - mm[mt][1] * u1) + wv1;
                        part[mt][0] += gelu_exact(h00) * w20 + gelu_exact(h01) * w21;
                        part[mt][1] += gelu_exact(h10) * w20 + gelu_exact(h11) * w21;
                        acc[mt][nt2][0] = 0.f; acc[mt][nt2][1] = 0.f;
                        acc[mt][nt2][2] = 0.f; acc[mt][nt2][3] = 0.f;
                    }
                }
#pragma unroll
                for (int off = 1; off <= 2; off <<= 1) {
#pragma unroll
                    for (int mt = 0; mt < 4; mt++) {
                        part[mt][0] += __shfl_xor_sync(full, part[mt][0], off);
                        part[mt][1] += __shfl_xor_sync(full, part[mt][1], off);
                    }
                }
                float* sr = (float*)(smem + SRED_OFF);
                if (tig == 0) {
#pragma unroll
                    for (int mt = 0; mt < 4; mt++) {
                        int r = warp_m * 64 + mt * 16 + g;
                        sr[warp_n * 128 + r] = part[mt][0];
                        sr[warp_n * 128 + r + 8] = part[mt][1];
                    }
                }
                __syncthreads();
                if (tid < 128)
                    dotacc += ((sr[tid] + sr[128 + tid]) + (sr[256 + tid] + sr[384 + tid]));
                __syncthreads();
            }
            if (more) { CP_WAIT0(); __syncthreads(); }
        }
    }

    // ================== FINALIZE TAIL (4 batches per CTA) ==================
    // slog: 128 logits; kern doubles after it (aligned, sred region is free now)
    float* slog = (float*)(smem + SRED_OFF);
    double* kern_s = (double*)(smem + SRED_OFF + 512);   // [0..4]=kern, [5..9]=raw
    if (tid < 128) slog[tid] = dotacc + b2[0];
    if (tid < 5) {
        double sigma = (double)(*sigma_ptr);
        double x = (double)(tid - 2) / sigma;
        kern_s[5 + tid] = exp(-0.5 * x * x);
    }
    __syncthreads();
    if (tid < 5) {
        double ks = kern_s[5] + kern_s[6] + kern_s[7] + kern_s[8] + kern_s[9];
        kern_s[tid] = kern_s[5 + tid] / ks;
    }
    __syncthreads();

    if (wid < 4) {
        double kern[5];
#pragma unroll
        for (int j = 0; j < 5; j++) kern[j] = kern_s[j];

        int b = (bm >> 5) + wid;            // global batch index
        float logit_f = slog[wid * 32 + lane];
        double logit = (double)logit_f;

        double m = logit;
        for (int o = 16; o; o >>= 1) m = fmax(m, __shfl_xor_sync(full, m, o));
        double e = exp(logit - m);
        double s = e;
        for (int o = 16; o; o >>= 1) s += __shfl_xor_sync(full, s, o);
        double kp = e / s;

        double sm = 0.0;
#pragma unroll
        for (int j = 0; j < 5; j++) {
            int src = lane + j - 2;
            double vsh = __shfl_sync(full, kp, src & 31);
            if (src >= 0 && src < LEN) sm += kern[j] * vsh;
        }

        double mg = sm;
        for (int o = 16; o; o >>= 1) mg = fmax(mg, __shfl_xor_sync(full, mg, o));
        double eg = exp(sm - mg);
        double sg = eg;
        for (int o = 16; o; o >>= 1) sg += __shfl_xor_sync(full, sg, o);
        double gs = eg / sg;

        double bv = gs; int bi = lane;
        for (int o = 16; o; o >>= 1) {
            double ov = __shfl_xor_sync(full, bv, o);
            int    oi = __shfl_xor_sync(full, bi, o);
            if (ov > bv || (ov == bv && oi < bi)) { bv = ov; bi = oi; }
        }
        int amax = bi;

        double cs = gs;
#pragma unroll
        for (int off = 1; off < 32; off <<= 1) {
            double t = __shfl_up_sync(full, cs, off);
            if (lane >= off) cs += t;
        }

        double bestv = -INFINITY;
        int bestc = 1 << 20;
#pragma unroll
        for (int r = 0; r < 3; r++) {
            int c = lane + r * 32;
            int w, st;
            if (c < 32)      { w = 1; st = c; }
            else if (c < 62) { w = 3; st = c - 32; }
            else             { w = 5; st = c - 62; }
            bool valid = (c < 90);
            double hi = __shfl_sync(full, cs, (st + w - 1) & 31);
            double lo = __shfl_sync(full, cs, (st - 1) & 31);
            double sum = hi - ((st > 0) ? lo : 0.0);
            bool contains = (amax >= st) && (amax < st + w);
            double val = (valid && contains) ? sum : -INFINITY;
            if (val > bestv || (val == bestv && c < bestc)) { bestv = val; bestc = c; }
        }
        for (int off = 16; off; off >>= 1) {
            double ov = __shfl_xor_sync(full, bestv, off);
            int    oc = __shfl_xor_sync(full, bestc, off);
            if (ov > bestv || (ov == bestv && oc < bestc)) { bestv = ov; bestc = oc; }
        }
        int s0, e0;
        {
            int c = bestc, w, st;
            if (c < 32)      { w = 1; st = c; }
            else if (c < 62) { w = 3; st = c - 32; }
            else             { w = 5; st = c - 62; }
            s0 = st; e0 = st + w;
        }

        out[OFF_GS + b * LEN + lane] = (float)gs;
        if (lane == 0) {
            out[OFF_MAXIDX + b * 2 + 0] = (float)s0;
            out[OFF_MAXIDX + b * 2 + 1] = (float)e0;
            out[OFF_START + b] = (float)s0 / 31.0f;
            out[OFF_END + b]   = (float)e0 / 31.0f;
        }
        out[OFF_MASK + b * LEN + lane] = (lane >= s0 && lane <= e0) ? 1.f : 0.f;
        out[OFF_ORIKEY + b * LEN + lane] = logit_f;
    }
}

// ---------------- launch ----------------------------------------------------
extern "C" void kernel_launch(void* const* d_in, const int* in_sizes, int n_in,
                              void* d_out, int out_size) {
    const float* v       = (const float*)d_in[0];
    const float* qa      = (const float*)d_in[1];
    const float* vp_g    = (const float*)d_in[2];
    const float* vp_b    = (const float*)d_in[3];
    const float* vp_W    = (const float*)d_in[4];
    const float* vp_bias = (const float*)d_in[5];
    const float* qp_g    = (const float*)d_in[6];
    const float* qp_b    = (const float*)d_in[7];
    const float* qp_W    = (const float*)d_in[8];
    const float* qp_bias = (const float*)d_in[9];
    const float* gr_g    = (const float*)d_in[10];
    const float* gr_b    = (const float*)d_in[11];
    const float* gr_W1   = (const float*)d_in[12];
    const float* gr_b1   = (const float*)d_in[13];
    const float* gr_W2   = (const float*)d_in[14];
    const float* gr_b2   = (const float*)d_in[15];
    const float* sigma   = (const float*)d_in[16];
    float* out = (float*)d_out;

    void *p_qa2, *p_u, *p_w;
    void *p_vs, *p_qs, *p_y, *p_vpw, *p_qpw, *p_w1;
    cudaGetSymbolAddress(&p_qa2, g_qa2);
    cudaGetSymbolAddress(&p_u,   g_u);
    cudaGetSymbolAddress(&p_w,   g_w);
    cudaGetSymbolAddress(&p_vs,  g_vs);
    cudaGetSymbolAddress(&p_qs,  g_qs);
    cudaGetSymbolAddress(&p_y,   g_y);
    cudaGetSymbolAddress(&p_vpw, g_vpW_s);
    cudaGetSymbolAddress(&p_qpw, g_qpW_s);
    cudaGetSymbolAddress(&p_w1,  g_grW1_s);

    __half* vs  = (__half*)p_vs;
    __half* qs  = (__half*)p_qs;
    __half* yy  = (__half*)p_y;
    __half* vpw = (__half*)p_vpw;
    __half* qpw = (__half*)p_qpw;
    __half* w1s = (__half*)p_w1;
    const size_t VN = (size_t)ROWS * DIM;
    const size_t QN = (size_t)BS * DIM;

    cudaFuncSetAttribute((const void*)stage2_kernel,
                         cudaFuncAttributeMaxDynamicSharedMemorySize, SMEM_DYN);
    cudaFuncSetAttribute((const void*)fused_gemm_kernel,
                         cudaFuncAttributeMaxDynamicSharedMemorySize, SMEM_DYN);

    // [1] transposes + LN-split(qa) + u/w (all independent, one launch)
    prep_stage1<<<S1_BLOCKS, 256>>>(
        vp_W, qp_W, gr_W1, vpw, qpw, w1s,
        qa, qp_g, qp_b, qs, qs + QN,
        gr_g, gr_b, gr_b1, (float*)p_u, (float*)p_w);

    // [2] qa2 GEMM tiles + LN-split(v) co-scheduled (tensor + memory overlap)
    stage2_kernel<<<S2_BLOCKS, 256, SMEM_DYN>>>(
        qs, qs + QN, qpw, qpw + (size_t)DIM * DIM, qp_bias, (float*)p_qa2,
        v, vp_g, vp_b, vs, vs + VN);

    // [3] fused GEMM1+GEMM3 + finalize tail (everything downstream in-CTA)
    fused_gemm_kernel<<<ROWS / 128, 256, SMEM_DYN>>>(
        vs, vs + VN, vpw, vpw + (size_t)DIM * DIM,
        w1s, w1s + (size_t)HID * DIM,
        vp_bias, gr_g, (const float*)p_qa2,
        yy, yy + VN,
        (const float*)p_u, (const float*)p_w,
        gr_W2, gr_b2, sigma, out);
}